// round 1
// baseline (speedup 1.0000x reference)
#include <cuda_runtime.h>
#include <cuda_bf16.h>
#include <math.h>

#define B   32
#define N   100
#define H   256
#define HA  1024
#define HC  512
#define KA  5000
#define NN  10000
#define F   356            // H + N feature width
#define EF_BSTRIDE (101 * 356)
#define OUT_FILLED 320000  // B * NN

// ---------------- scratch (device globals: allowed, no allocs) ----------------
__device__ int   g_idx[B * KA];              // ordered active flat indices
__device__ float g_base1[B * HA];            // g @ aW1[0:256] + ab1
__device__ float g_P1[B * N * HA];           // nodes @ aW1[256:512]
__device__ float g_P2[B * N * HA];           // nodes @ aW1[512:768]
__device__ float g_Y1[B * KA * HA];          // 655 MB: tanh(base1 + P1[i1] + P2[i2])
__device__ float g_logits[B * KA];

// ---------------- kernel 1: ordered compaction of mask indices ----------------
__global__ void k_extract(const float* __restrict__ ef) {
    int b = blockIdx.x;
    int lane = threadIdx.x;
    const float* base = ef + (size_t)b * EF_BSTRIDE;
    int cnt = 0;
    for (int j0 = 0; j0 < NN; j0 += 32) {
        int j = j0 + lane;
        bool act = false;
        if (j < NN) {
            int i = j / N;
            int c = j - i * N;
            float v = base[(size_t)(1 + i) * F + H + c];
            act = (v > 0.5f);
        }
        unsigned m = __ballot_sync(0xffffffffu, act);
        if (act) {
            int pos = cnt + __popc(m & ((1u << lane) - 1u));
            if (pos < KA) g_idx[b * KA + pos] = j;
        }
        cnt += __popc(m);
    }
}

// ---------------- kernel 2: base1 = g @ aW1[0:256] + ab1 ----------------
__global__ void k_base1(const float* __restrict__ ef,
                        const float* __restrict__ aW1,
                        const float* __restrict__ ab1) {
    __shared__ float sg[H];
    int b = blockIdx.x;
    int o = blockIdx.y * 256 + threadIdx.x;
    if (threadIdx.x < H) sg[threadIdx.x] = ef[(size_t)b * EF_BSTRIDE + threadIdx.x];
    __syncthreads();
    float acc = ab1[o];
#pragma unroll 8
    for (int h = 0; h < H; h++) acc += sg[h] * aW1[(size_t)h * HA + o];
    g_base1[b * HA + o] = acc;
}

// ---------------- kernel 3: P1/P2 GEMM  (3200x256)@(256x1024), shared A tile ----------------
__global__ void __launch_bounds__(256) k_pgemm(const float* __restrict__ ef,
                                               const float* __restrict__ aW1) {
    __shared__ float As[16][68];
    __shared__ float W1s[16][64];
    __shared__ float W2s[16][64];
    int tid = threadIdx.x;
    int tx = tid & 15, ty = tid >> 4;
    int r0 = blockIdx.x * 64;
    int c0 = blockIdx.y * 64;

    float acc1[4][4], acc2[4][4];
#pragma unroll
    for (int i = 0; i < 4; i++)
#pragma unroll
        for (int j = 0; j < 4; j++) { acc1[i][j] = 0.f; acc2[i][j] = 0.f; }

    int lrow = tid >> 2;            // 0..63
    int lk4  = (tid & 3) * 4;
    int grow = r0 + lrow;
    int gb = grow / N;
    int gn = grow - gb * N;
    const float* aptr = ef + (size_t)gb * EF_BSTRIDE + (size_t)(1 + gn) * F;
    int wkr = tid >> 4;             // 0..15
    int wc4 = (tid & 15) * 4;

    for (int k0 = 0; k0 < H; k0 += 16) {
        float4 av = *(const float4*)(aptr + k0 + lk4);
        float4 w1 = *(const float4*)(aW1 + (size_t)(H + k0 + wkr) * HA + c0 + wc4);
        float4 w2 = *(const float4*)(aW1 + (size_t)(2 * H + k0 + wkr) * HA + c0 + wc4);
        As[lk4 + 0][lrow] = av.x; As[lk4 + 1][lrow] = av.y;
        As[lk4 + 2][lrow] = av.z; As[lk4 + 3][lrow] = av.w;
        *(float4*)&W1s[wkr][wc4] = w1;
        *(float4*)&W2s[wkr][wc4] = w2;
        __syncthreads();
#pragma unroll
        for (int k = 0; k < 16; k++) {
            float a[4], b1[4], b2[4];
            *(float4*)a  = *(const float4*)&As[k][ty * 4];
            *(float4*)b1 = *(const float4*)&W1s[k][tx * 4];
            *(float4*)b2 = *(const float4*)&W2s[k][tx * 4];
#pragma unroll
            for (int i = 0; i < 4; i++)
#pragma unroll
                for (int j = 0; j < 4; j++) {
                    acc1[i][j] += a[i] * b1[j];
                    acc2[i][j] += a[i] * b2[j];
                }
        }
        __syncthreads();
    }
#pragma unroll
    for (int i = 0; i < 4; i++) {
        int row = r0 + ty * 4 + i;
        float* p1 = g_P1 + (size_t)row * HA + c0 + tx * 4;
        float* p2 = g_P2 + (size_t)row * HA + c0 + tx * 4;
        *(float4*)p1 = make_float4(acc1[i][0], acc1[i][1], acc1[i][2], acc1[i][3]);
        *(float4*)p2 = make_float4(acc2[i][0], acc2[i][1], acc2[i][2], acc2[i][3]);
    }
}

// ---------------- kernel 4: Y1 = tanh(base1 + P1[i1] + P2[i2]) ----------------
__global__ void k_y1() {
    int row = blockIdx.x;            // 0..159999
    int b = row / KA;
    int id = g_idx[row];
    int i1 = id / N;
    int i2 = id - i1 * N;
    const float4* p1 = (const float4*)(g_P1 + (size_t)(b * N + i1) * HA);
    const float4* p2 = (const float4*)(g_P2 + (size_t)(b * N + i2) * HA);
    const float4* bs = (const float4*)(g_base1 + (size_t)b * HA);
    float4* y = (float4*)(g_Y1 + (size_t)row * HA);
    int t = threadIdx.x;             // 256 threads -> 256 float4 = 1024 floats
    float4 a = p1[t], c = p2[t], d = bs[t];
    float4 r;
    r.x = tanhf(a.x + c.x + d.x);
    r.y = tanhf(a.y + c.y + d.y);
    r.z = tanhf(a.z + c.z + d.z);
    r.w = tanhf(a.w + c.w + d.w);
    y[t] = r;
}

// ---------------- kernel 5: layer2 GEMM fused with layer3 dot -> logits ----------------
// CTA: 128 rows, internal loop over 8 col-tiles of 128; 256 threads, 8x8 micro-tile.
__global__ void __launch_bounds__(256) k_l23(const float* __restrict__ aW2,
                                             const float* __restrict__ ab2,
                                             const float* __restrict__ aW3,
                                             const float* __restrict__ ab3) {
    __shared__ float As[16][132];
    __shared__ float Bs[16][128];
    __shared__ float red[16][129];
    int tid = threadIdx.x;
    int tx = tid & 15, ty = tid >> 4;
    size_t r0 = (size_t)blockIdx.x * 128;

    float lpart[8];
#pragma unroll
    for (int i = 0; i < 8; i++) lpart[i] = 0.f;

    int arow = tid >> 2;             // 0..63
    int ak4  = (tid & 3) * 4;
    const float* aptr0 = g_Y1 + (r0 + arow) * HA + ak4;
    const float* aptr1 = g_Y1 + (r0 + arow + 64) * HA + ak4;
    int bkr = tid >> 5;              // 0..7
    int bc4 = (tid & 31) * 4;

    for (int ct = 0; ct < 8; ct++) {
        int c0 = ct * 128;
        float acc[8][8];
#pragma unroll
        for (int i = 0; i < 8; i++)
#pragma unroll
            for (int j = 0; j < 8; j++) acc[i][j] = 0.f;

        for (int k0 = 0; k0 < HA; k0 += 16) {
            float4 a0 = *(const float4*)(aptr0 + k0);
            float4 a1 = *(const float4*)(aptr1 + k0);
            float4 b0 = *(const float4*)(aW2 + (size_t)(k0 + bkr) * HA + c0 + bc4);
            float4 b1v = *(const float4*)(aW2 + (size_t)(k0 + bkr + 8) * HA + c0 + bc4);
            As[ak4 + 0][arow] = a0.x; As[ak4 + 1][arow] = a0.y;
            As[ak4 + 2][arow] = a0.z; As[ak4 + 3][arow] = a0.w;
            As[ak4 + 0][arow + 64] = a1.x; As[ak4 + 1][arow + 64] = a1.y;
            As[ak4 + 2][arow + 64] = a1.z; As[ak4 + 3][arow + 64] = a1.w;
            *(float4*)&Bs[bkr][bc4] = b0;
            *(float4*)&Bs[bkr + 8][bc4] = b1v;
            __syncthreads();
#pragma unroll
            for (int k = 0; k < 16; k++) {
                float a[8], bb[8];
                *(float4*)(a)     = *(const float4*)&As[k][ty * 8];
                *(float4*)(a + 4) = *(const float4*)&As[k][ty * 8 + 4];
                *(float4*)(bb)     = *(const float4*)&Bs[k][tx * 8];
                *(float4*)(bb + 4) = *(const float4*)&Bs[k][tx * 8 + 4];
#pragma unroll
                for (int i = 0; i < 8; i++)
#pragma unroll
                    for (int j = 0; j < 8; j++)
                        acc[i][j] += a[i] * bb[j];
            }
            __syncthreads();
        }
        // epilogue for this col-tile: tanh + dot with aW3 slice
#pragma unroll
        for (int j = 0; j < 8; j++) {
            int c = c0 + tx * 8 + j;
            float w3 = aW3[c];
            float bias = ab2[c];
#pragma unroll
            for (int i = 0; i < 8; i++)
                lpart[i] += tanhf(acc[i][j] + bias) * w3;
        }
    }
    // reduce partial logits across the 16 tx-threads per row
#pragma unroll
    for (int i = 0; i < 8; i++) red[tx][ty * 8 + i] = lpart[i];
    __syncthreads();
    if (tid < 128) {
        float s = 0.f;
#pragma unroll
        for (int t = 0; t < 16; t++) s += red[t][tid];
        g_logits[r0 + tid] = s + ab3[0];
    }
}

// ---------------- kernel 6: zero filled region ----------------
__global__ void k_zero(float* __restrict__ out) {
    int i = blockIdx.x * blockDim.x + threadIdx.x;
    if (i < OUT_FILLED) out[i] = 0.f;
}

// ---------------- kernel 7: softmax over K per batch + scatter ----------------
__global__ void k_softmax(float* __restrict__ out) {
    int b = blockIdx.x;
    int tid = threadIdx.x;           // 1024
    __shared__ float sred[32];
    __shared__ float sbcast;
    const float* lg = g_logits + b * KA;

    float m = -3.4e38f;
    for (int k = tid; k < KA; k += 1024) m = fmaxf(m, lg[k]);
#pragma unroll
    for (int o = 16; o; o >>= 1) m = fmaxf(m, __shfl_xor_sync(0xffffffffu, m, o));
    if ((tid & 31) == 0) sred[tid >> 5] = m;
    __syncthreads();
    if (tid < 32) {
        float v = sred[tid];
#pragma unroll
        for (int o = 16; o; o >>= 1) v = fmaxf(v, __shfl_xor_sync(0xffffffffu, v, o));
        if (tid == 0) sbcast = v;
    }
    __syncthreads();
    float gmax = sbcast;

    float s = 0.f;
    for (int k = tid; k < KA; k += 1024) s += expf(lg[k] - gmax);
#pragma unroll
    for (int o = 16; o; o >>= 1) s += __shfl_xor_sync(0xffffffffu, s, o);
    if ((tid & 31) == 0) sred[tid >> 5] = s;
    __syncthreads();
    if (tid < 32) {
        float v = sred[tid];
#pragma unroll
        for (int o = 16; o; o >>= 1) v += __shfl_xor_sync(0xffffffffu, v, o);
        if (tid == 0) sbcast = v;
    }
    __syncthreads();
    float inv = 1.0f / sbcast;

    for (int k = tid; k < KA; k += 1024) {
        int j = g_idx[b * KA + k];
        out[(size_t)b * NN + j] = expf(lg[k] - gmax) * inv;
    }
}

// ---------------- kernel 8: value head (tiny) ----------------
__global__ void k_value(const float* __restrict__ ef,
                        const float* __restrict__ cW1, const float* __restrict__ cb1,
                        const float* __restrict__ cW2, const float* __restrict__ cb2,
                        const float* __restrict__ cW3, const float* __restrict__ cb3,
                        float* __restrict__ out) {
    __shared__ float sg[H];
    __shared__ float h1[HC];
    __shared__ float h2[HC];
    __shared__ float sr[16];
    int b = blockIdx.x;
    int tid = threadIdx.x;           // 512
    if (tid < H) sg[tid] = ef[(size_t)b * EF_BSTRIDE + tid];
    __syncthreads();
    float acc = cb1[tid];
#pragma unroll 8
    for (int h = 0; h < H; h++) acc += sg[h] * cW1[h * HC + tid];
    h1[tid] = tanhf(acc);
    __syncthreads();
    float acc2 = cb2[tid];
#pragma unroll 8
    for (int h = 0; h < HC; h++) acc2 += h1[h] * cW2[h * HC + tid];
    h2[tid] = tanhf(acc2);
    __syncthreads();
    float p = h2[tid] * cW3[tid];
#pragma unroll
    for (int o = 16; o; o >>= 1) p += __shfl_xor_sync(0xffffffffu, p, o);
    if ((tid & 31) == 0) sr[tid >> 5] = p;
    __syncthreads();
    if (tid < 16) {
        float v = sr[tid];
#pragma unroll
        for (int o = 8; o; o >>= 1) v += __shfl_xor_sync(0x0000ffffu, v, o);
        if (tid == 0) out[OUT_FILLED + b] = v + cb3[0];
    }
}

// ---------------- launch ----------------
extern "C" void kernel_launch(void* const* d_in, const int* in_sizes, int n_in,
                              void* d_out, int out_size) {
    const float* ef  = (const float*)d_in[0];
    const float* aW1 = (const float*)d_in[1];
    const float* ab1 = (const float*)d_in[2];
    const float* aW2 = (const float*)d_in[3];
    const float* ab2 = (const float*)d_in[4];
    const float* aW3 = (const float*)d_in[5];
    const float* ab3 = (const float*)d_in[6];
    const float* cW1 = (const float*)d_in[7];
    const float* cb1 = (const float*)d_in[8];
    const float* cW2 = (const float*)d_in[9];
    const float* cb2 = (const float*)d_in[10];
    const float* cW3 = (const float*)d_in[11];
    const float* cb3 = (const float*)d_in[12];
    float* out = (float*)d_out;

    k_extract<<<B, 32>>>(ef);
    k_base1<<<dim3(B, 4), 256>>>(ef, aW1, ab1);
    k_pgemm<<<dim3(50, 16), 256>>>(ef, aW1);
    k_y1<<<B * KA, 256>>>();
    k_l23<<<1250, 256>>>(aW2, ab2, aW3, ab3);
    k_zero<<<625, 512>>>(out);
    k_value<<<B, 512>>>(ef, cW1, cb1, cW2, cb2, cW3, cb3, out);
    k_softmax<<<B, 1024>>>(out);
}

// round 3
// speedup vs baseline: 2.2682x; 2.2682x over previous
#include <cuda_runtime.h>
#include <cuda_bf16.h>
#include <math.h>
#include <stdint.h>

#define B   32
#define N   100
#define H   256
#define HA  1024
#define HC  512
#define KA  5000
#define NN  10000
#define F   356
#define EF_BSTRIDE (101 * 356)
#define OUT_FILLED 320000

// ---------------- scratch ----------------
__device__ int   g_idx[B * KA];
__device__ float g_base1[B * HA];
__device__ float g_P1[B * N * HA];
__device__ float g_P2[B * N * HA];
__device__ float g_Y1[(size_t)B * KA * HA];   // 655 MB, tf32-rounded
__device__ float g_W2t[HA * HA];              // aW2 transposed [n][k], tf32-rounded
__device__ float g_logits[B * KA];

// ---------------- helpers ----------------
__device__ __forceinline__ uint32_t s2u(const void* p) {
    return (uint32_t)__cvta_generic_to_shared(p);
}
__device__ __forceinline__ float to_tf32(float x) {
    uint32_t u;
    asm("cvt.rna.tf32.f32 %0, %1;" : "=r"(u) : "f"(x));
    return __uint_as_float(u);
}
#define CPA16(dst, src) asm volatile("cp.async.cg.shared.global [%0], [%1], 16;" :: "r"(dst), "l"(src) : "memory")
#define CPA_COMMIT()    asm volatile("cp.async.commit_group;" ::: "memory")
#define CPA_WAIT(n)     asm volatile("cp.async.wait_group %0;" :: "n"(n) : "memory")

__device__ __forceinline__ void mma_tf32(float* c, const uint32_t* a, const uint32_t* b) {
    asm volatile("mma.sync.aligned.m16n8k8.row.col.f32.tf32.tf32.f32 "
        "{%0,%1,%2,%3}, {%4,%5,%6,%7}, {%8,%9}, {%0,%1,%2,%3};"
        : "+f"(c[0]), "+f"(c[1]), "+f"(c[2]), "+f"(c[3])
        : "r"(a[0]), "r"(a[1]), "r"(a[2]), "r"(a[3]), "r"(b[0]), "r"(b[1]));
}

// ---------------- kernel 1: ordered compaction ----------------
__global__ void k_extract(const float* __restrict__ ef) {
    int b = blockIdx.x;
    int lane = threadIdx.x;
    const float* base = ef + (size_t)b * EF_BSTRIDE;
    int cnt = 0;
    for (int j0 = 0; j0 < NN; j0 += 32) {
        int j = j0 + lane;
        int i = j / N;
        int c = j - i * N;
        float v = base[(size_t)(1 + i) * F + H + c];
        bool act = (v > 0.5f);
        unsigned m = __ballot_sync(0xffffffffu, act);
        if (act) {
            int pos = cnt + __popc(m & ((1u << lane) - 1u));
            if (pos < KA) g_idx[b * KA + pos] = j;
        }
        cnt += __popc(m);
    }
}

// ---------------- kernel 2: base1 ----------------
__global__ void k_base1(const float* __restrict__ ef,
                        const float* __restrict__ aW1,
                        const float* __restrict__ ab1) {
    __shared__ float sg[H];
    int b = blockIdx.x;
    int o = blockIdx.y * 256 + threadIdx.x;
    if (threadIdx.x < H) sg[threadIdx.x] = ef[(size_t)b * EF_BSTRIDE + threadIdx.x];
    __syncthreads();
    float acc = ab1[o];
#pragma unroll 8
    for (int h = 0; h < H; h++) acc += sg[h] * aW1[(size_t)h * HA + o];
    g_base1[b * HA + o] = acc;
}

// ---------------- kernel 3: P1/P2 GEMM (fp32) ----------------
__global__ void __launch_bounds__(256) k_pgemm(const float* __restrict__ ef,
                                               const float* __restrict__ aW1) {
    __shared__ float As[16][68];
    __shared__ float W1s[16][64];
    __shared__ float W2s[16][64];
    int tid = threadIdx.x;
    int tx = tid & 15, ty = tid >> 4;
    int r0 = blockIdx.x * 64;
    int c0 = blockIdx.y * 64;

    float acc1[4][4], acc2[4][4];
#pragma unroll
    for (int i = 0; i < 4; i++)
#pragma unroll
        for (int j = 0; j < 4; j++) { acc1[i][j] = 0.f; acc2[i][j] = 0.f; }

    int lrow = tid >> 2;
    int lk4  = (tid & 3) * 4;
    int grow = r0 + lrow;
    int gb = grow / N;
    int gn = grow - gb * N;
    const float* aptr = ef + (size_t)gb * EF_BSTRIDE + (size_t)(1 + gn) * F;
    int wkr = tid >> 4;
    int wc4 = (tid & 15) * 4;

    for (int k0 = 0; k0 < H; k0 += 16) {
        float4 av = *(const float4*)(aptr + k0 + lk4);
        float4 w1 = *(const float4*)(aW1 + (size_t)(H + k0 + wkr) * HA + c0 + wc4);
        float4 w2 = *(const float4*)(aW1 + (size_t)(2 * H + k0 + wkr) * HA + c0 + wc4);
        As[lk4 + 0][lrow] = av.x; As[lk4 + 1][lrow] = av.y;
        As[lk4 + 2][lrow] = av.z; As[lk4 + 3][lrow] = av.w;
        *(float4*)&W1s[wkr][wc4] = w1;
        *(float4*)&W2s[wkr][wc4] = w2;
        __syncthreads();
#pragma unroll
        for (int k = 0; k < 16; k++) {
            float a[4], b1[4], b2[4];
            *(float4*)a  = *(const float4*)&As[k][ty * 4];
            *(float4*)b1 = *(const float4*)&W1s[k][tx * 4];
            *(float4*)b2 = *(const float4*)&W2s[k][tx * 4];
#pragma unroll
            for (int i = 0; i < 4; i++)
#pragma unroll
                for (int j = 0; j < 4; j++) {
                    acc1[i][j] += a[i] * b1[j];
                    acc2[i][j] += a[i] * b2[j];
                }
        }
        __syncthreads();
    }
#pragma unroll
    for (int i = 0; i < 4; i++) {
        int row = r0 + ty * 4 + i;
        float* p1 = g_P1 + (size_t)row * HA + c0 + tx * 4;
        float* p2 = g_P2 + (size_t)row * HA + c0 + tx * 4;
        *(float4*)p1 = make_float4(acc1[i][0], acc1[i][1], acc1[i][2], acc1[i][3]);
        *(float4*)p2 = make_float4(acc2[i][0], acc2[i][1], acc2[i][2], acc2[i][3]);
    }
}

// ---------------- kernel 3b: transpose aW2 -> g_W2t[n][k], tf32-rounded ----------------
__global__ void k_tw2(const float* __restrict__ aW2) {
    __shared__ float t[32][33];
    int bx = blockIdx.x * 32, by = blockIdx.y * 32;
    int x = threadIdx.x, y = threadIdx.y;  // 32 x 8
    for (int yy = y; yy < 32; yy += 8)
        t[yy][x] = aW2[(size_t)(by + yy) * HA + bx + x];
    __syncthreads();
    for (int yy = y; yy < 32; yy += 8)
        g_W2t[(size_t)(bx + yy) * HA + by + x] = to_tf32(t[x][yy]);
}

// ---------------- kernel 4: Y1 = tf32(tanh(base1 + P1[i1] + P2[i2])) ----------------
__global__ void k_y1() {
    int row = blockIdx.x;
    int b = row / KA;
    int id = g_idx[row];
    int i1 = id / N;
    int i2 = id - i1 * N;
    const float4* p1 = (const float4*)(g_P1 + (size_t)(b * N + i1) * HA);
    const float4* p2 = (const float4*)(g_P2 + (size_t)(b * N + i2) * HA);
    const float4* bs = (const float4*)(g_base1 + (size_t)b * HA);
    float4* y = (float4*)(g_Y1 + (size_t)row * HA);
    int t = threadIdx.x;
    float4 a = p1[t], c = p2[t], d = bs[t];
    float4 r;
    r.x = to_tf32(tanhf(a.x + c.x + d.x));
    r.y = to_tf32(tanhf(a.y + c.y + d.y));
    r.z = to_tf32(tanhf(a.z + c.z + d.z));
    r.w = to_tf32(tanhf(a.w + c.w + d.w));
    y[t] = r;
}

// ---------------- kernel 5: HMMA tf32 layer2 GEMM + fused layer3 ----------------
// CTA: 128 rows x (8 col-tiles of 128), K=1024. 8 warps (2x4), warp tile 64x32.
// smem: 2 stages x (A[128][20] + B[128][20]) + ab2 + w3 + red = 51200 B dynamic.
#define L23_SMEM 51200
extern __shared__ __align__(16) float smf[];

__global__ void __launch_bounds__(256, 1) k_l23(const float* __restrict__ ab2,
                                                const float* __restrict__ aW3) {
    const int tid = threadIdx.x;
    const int wid = tid >> 5;
    const int lane = tid & 31;
    const int wy = wid >> 2;     // 0..1, row band of 64
    const int wx = wid & 3;      // 0..3, col band of 32
    const size_t r0 = (size_t)blockIdx.x * 128;

    float* sab2 = smf + 10240;
    float* sw3  = smf + 11264;
    float* sred = smf + 12288;   // [4][128]
    const uint32_t su = s2u(smf);

#pragma unroll
    for (int i = tid; i < 1024; i += 256) {
        sab2[i] = ab2[i];
        sw3[i]  = aW3[i];
    }

    const int gq = lane >> 2;    // groupID 0..7
    const int gt = lane & 3;     // threadID-in-group 0..3

    float lsum[8];
#pragma unroll
    for (int i = 0; i < 8; i++) lsum[i] = 0.f;

    const float* Abase = g_Y1 + r0 * HA;

    for (int ct = 0; ct < 8; ct++) {
        const float* Bbase = g_W2t + (size_t)(ct * 128) * HA;
        float acc[4][4][4];
#pragma unroll
        for (int mt = 0; mt < 4; mt++)
#pragma unroll
            for (int nt = 0; nt < 4; nt++)
#pragma unroll
                for (int r = 0; r < 4; r++) acc[mt][nt][r] = 0.f;

        // preload kt=0 into stage 0
        {
#pragma unroll
            for (int it = 0; it < 2; it++) {
                int idx = tid + it * 256;
                int m = idx >> 2, c4 = idx & 3;
                uint32_t so = (uint32_t)(m * 80 + c4 * 16);
                CPA16(su + so,         Abase + (size_t)m * HA + c4 * 4);
                CPA16(su + 10240 + so, Bbase + (size_t)m * HA + c4 * 4);
            }
            CPA_COMMIT();
        }

        for (int kt = 0; kt < 64; kt++) {
            const int s = kt & 1;
            if (kt < 63) {
                const int k0n = (kt + 1) * 16;
                const uint32_t sb = su + (s ^ 1) * 20480;
#pragma unroll
                for (int it = 0; it < 2; it++) {
                    int idx = tid + it * 256;
                    int m = idx >> 2, c4 = idx & 3;
                    uint32_t so = (uint32_t)(m * 80 + c4 * 16);
                    CPA16(sb + so,         Abase + (size_t)m * HA + k0n + c4 * 4);
                    CPA16(sb + 10240 + so, Bbase + (size_t)m * HA + k0n + c4 * 4);
                }
                CPA_COMMIT();
                CPA_WAIT(1);
            } else {
                CPA_WAIT(0);
            }
            __syncthreads();

            const float* A   = smf + s * 5120;
            const float* Bsm = smf + s * 5120 + 2560;
#pragma unroll
            for (int k8 = 0; k8 < 2; k8++) {
                const int c = k8 * 8 + gt;
                uint32_t af[4][4];
#pragma unroll
                for (int mt = 0; mt < 4; mt++) {
                    int r = wy * 64 + mt * 16 + gq;
                    af[mt][0] = __float_as_uint(A[r * 20 + c]);
                    af[mt][1] = __float_as_uint(A[(r + 8) * 20 + c]);
                    af[mt][2] = __float_as_uint(A[r * 20 + c + 4]);
                    af[mt][3] = __float_as_uint(A[(r + 8) * 20 + c + 4]);
                }
                uint32_t bf[4][2];
#pragma unroll
                for (int nt = 0; nt < 4; nt++) {
                    int n = wx * 32 + nt * 8 + gq;
                    bf[nt][0] = __float_as_uint(Bsm[n * 20 + k8 * 8 + gt]);
                    bf[nt][1] = __float_as_uint(Bsm[n * 20 + k8 * 8 + gt + 4]);
                }
#pragma unroll
                for (int mt = 0; mt < 4; mt++)
#pragma unroll
                    for (int nt = 0; nt < 4; nt++)
                        mma_tf32(acc[mt][nt], af[mt], bf[nt]);
            }
            __syncthreads();
        }

        // fused layer-3 epilogue for this col-tile
#pragma unroll
        for (int mt = 0; mt < 4; mt++)
#pragma unroll
            for (int rr = 0; rr < 2; rr++) {
                float v = 0.f;
#pragma unroll
                for (int nt = 0; nt < 4; nt++) {
                    int col = ct * 128 + wx * 32 + nt * 8 + gt * 2;
                    float x0 = acc[mt][nt][rr * 2 + 0] + sab2[col];
                    float x1 = acc[mt][nt][rr * 2 + 1] + sab2[col + 1];
                    v += tanhf(x0) * sw3[col] + tanhf(x1) * sw3[col + 1];
                }
                lsum[mt * 2 + rr] += v;
            }
    }

    // reduce across quad lanes (cols) then across 4 col-band warps
#pragma unroll
    for (int i = 0; i < 8; i++) {
        float v = lsum[i];
        v += __shfl_xor_sync(0xffffffffu, v, 1);
        v += __shfl_xor_sync(0xffffffffu, v, 2);
        if (gt == 0) {
            int lr = wy * 64 + (i >> 1) * 16 + (i & 1) * 8 + gq;
            sred[wx * 128 + lr] = v;
        }
    }
    __syncthreads();
    if (tid < 128) {
        float v = (sred[tid] + sred[128 + tid]) + (sred[256 + tid] + sred[384 + tid]);
        g_logits[r0 + tid] = v;
    }
}

// ---------------- kernel 6: zero ----------------
__global__ void k_zero(float* __restrict__ out) {
    int i = blockIdx.x * blockDim.x + threadIdx.x;
    if (i < OUT_FILLED) out[i] = 0.f;
}

// ---------------- kernel 7: softmax + scatter ----------------
__global__ void k_softmax(float* __restrict__ out, const float* __restrict__ ab3) {
    __shared__ float slog[KA];
    __shared__ float sred2[32];
    __shared__ float sbcast;
    int b = blockIdx.x;
    int tid = threadIdx.x;  // 1024
    float b3 = ab3[0];
    for (int k = tid; k < KA; k += 1024)
        slog[k] = g_logits[b * KA + k] + b3;
    __syncthreads();

    float m = -3.4e38f;
    for (int k = tid; k < KA; k += 1024) m = fmaxf(m, slog[k]);
#pragma unroll
    for (int o = 16; o; o >>= 1) m = fmaxf(m, __shfl_xor_sync(0xffffffffu, m, o));
    if ((tid & 31) == 0) sred2[tid >> 5] = m;
    __syncthreads();
    if (tid < 32) {
        float v = sred2[tid];
#pragma unroll
        for (int o = 16; o; o >>= 1) v = fmaxf(v, __shfl_xor_sync(0xffffffffu, v, o));
        if (tid == 0) sbcast = v;
    }
    __syncthreads();
    float gmax = sbcast;

    float s = 0.f;
    for (int k = tid; k < KA; k += 1024) s += expf(slog[k] - gmax);
#pragma unroll
    for (int o = 16; o; o >>= 1) s += __shfl_xor_sync(0xffffffffu, s, o);
    if ((tid & 31) == 0) sred2[tid >> 5] = s;
    __syncthreads();
    if (tid < 32) {
        float v = sred2[tid];
#pragma unroll
        for (int o = 16; o; o >>= 1) v += __shfl_xor_sync(0xffffffffu, v, o);
        if (tid == 0) sbcast = v;
    }
    __syncthreads();
    float inv = 1.0f / sbcast;

    for (int k = tid; k < KA; k += 1024) {
        int j = g_idx[b * KA + k];
        out[(size_t)b * NN + j] = expf(slog[k] - gmax) * inv;
    }
}

// ---------------- kernel 8: value head ----------------
__global__ void k_value(const float* __restrict__ ef,
                        const float* __restrict__ cW1, const float* __restrict__ cb1,
                        const float* __restrict__ cW2, const float* __restrict__ cb2,
                        const float* __restrict__ cW3, const float* __restrict__ cb3,
                        float* __restrict__ out) {
    __shared__ float sg[H];
    __shared__ float h1[HC];
    __shared__ float h2[HC];
    __shared__ float sr[16];
    int b = blockIdx.x;
    int tid = threadIdx.x;  // 512
    if (tid < H) sg[tid] = ef[(size_t)b * EF_BSTRIDE + tid];
    __syncthreads();
    float acc = cb1[tid];
#pragma unroll 8
    for (int h = 0; h < H; h++) acc += sg[h] * cW1[h * HC + tid];
    h1[tid] = tanhf(acc);
    __syncthreads();
    float acc2 = cb2[tid];
#pragma unroll 8
    for (int h = 0; h < HC; h++) acc2 += h1[h] * cW2[h * HC + tid];
    h2[tid] = tanhf(acc2);
    __syncthreads();
    float p = h2[tid] * cW3[tid];
#pragma unroll
    for (int o = 16; o; o >>= 1) p += __shfl_xor_sync(0xffffffffu, p, o);
    if ((tid & 31) == 0) sr[tid >> 5] = p;
    __syncthreads();
    if (tid < 16) {
        float v = sr[tid];
#pragma unroll
        for (int o = 8; o; o >>= 1) v += __shfl_xor_sync(0x0000ffffu, v, o);
        if (tid == 0) out[OUT_FILLED + b] = v + cb3[0];
    }
}

// ---------------- launch ----------------
extern "C" void kernel_launch(void* const* d_in, const int* in_sizes, int n_in,
                              void* d_out, int out_size) {
    const float* ef  = (const float*)d_in[0];
    const float* aW1 = (const float*)d_in[1];
    const float* ab1 = (const float*)d_in[2];
    const float* aW2 = (const float*)d_in[3];
    const float* ab2 = (const float*)d_in[4];
    const float* aW3 = (const float*)d_in[5];
    const float* ab3 = (const float*)d_in[6];
    const float* cW1 = (const float*)d_in[7];
    const float* cb1 = (const float*)d_in[8];
    const float* cW2 = (const float*)d_in[9];
    const float* cb2 = (const float*)d_in[10];
    const float* cW3 = (const float*)d_in[11];
    const float* cb3 = (const float*)d_in[12];
    float* out = (float*)d_out;

    cudaFuncSetAttribute(k_l23, cudaFuncAttributeMaxDynamicSharedMemorySize, L23_SMEM);

    k_extract<<<B, 32>>>(ef);
    k_base1<<<dim3(B, 4), 256>>>(ef, aW1, ab1);
    k_pgemm<<<dim3(50, 16), 256>>>(ef, aW1);
    k_tw2<<<dim3(32, 32), dim3(32, 8)>>>(aW2);
    k_y1<<<B * KA, 256>>>();
    k_l23<<<1250, 256, L23_SMEM>>>(ab2, aW3);
    k_zero<<<625, 512>>>(out);
    k_value<<<B, 512>>>(ef, cW1, cb1, cW2, cb2, cW3, cb3, out);
    k_softmax<<<B, 1024>>>(out, ab3);
}

// round 4
// speedup vs baseline: 2.9418x; 1.2970x over previous
#include <cuda_runtime.h>
#include <cuda_bf16.h>
#include <math.h>
#include <stdint.h>

#define B   32
#define N   100
#define H   256
#define HA  1024
#define HC  512
#define KA  5000
#define NN  10000
#define F   356
#define EF_BSTRIDE (101 * 356)
#define OUT_FILLED 320000

// ---------------- scratch ----------------
__device__ int   g_idx[B * KA];
__device__ float g_base1[B * HA];
__device__ float g_P1[B * N * HA];
__device__ float g_P2[B * N * HA];
__device__ float g_Y1[(size_t)B * KA * HA];   // 655 MB, tf32-rounded
__device__ float g_W2t[HA * HA];              // aW2 transposed [n][k], tf32-rounded
__device__ float g_logits[B * KA];

// ---------------- helpers ----------------
__device__ __forceinline__ uint32_t s2u(const void* p) {
    return (uint32_t)__cvta_generic_to_shared(p);
}
__device__ __forceinline__ float to_tf32(float x) {
    uint32_t u;
    asm("cvt.rna.tf32.f32 %0, %1;" : "=r"(u) : "f"(x));
    return __uint_as_float(u);
}
__device__ __forceinline__ float tanh_fast(float x) {
    float r;
    asm("tanh.approx.f32 %0, %1;" : "=f"(r) : "f"(x));
    return r;
}
#define CPA16(dst, src) asm volatile("cp.async.cg.shared.global [%0], [%1], 16;" :: "r"(dst), "l"(src) : "memory")
#define CPA_COMMIT()    asm volatile("cp.async.commit_group;" ::: "memory")
#define CPA_WAIT(n)     asm volatile("cp.async.wait_group %0;" :: "n"(n) : "memory")

#define LDSM4(r0, r1, r2, r3, a) \
    asm volatile("ldmatrix.sync.aligned.m8n8.x4.shared.b16 {%0,%1,%2,%3}, [%4];" \
        : "=r"(r0), "=r"(r1), "=r"(r2), "=r"(r3) : "r"(a))

__device__ __forceinline__ void mma_tf32(float* c, const uint32_t* a, uint32_t b0, uint32_t b1) {
    asm volatile("mma.sync.aligned.m16n8k8.row.col.f32.tf32.tf32.f32 "
        "{%0,%1,%2,%3}, {%4,%5,%6,%7}, {%8,%9}, {%0,%1,%2,%3};"
        : "+f"(c[0]), "+f"(c[1]), "+f"(c[2]), "+f"(c[3])
        : "r"(a[0]), "r"(a[1]), "r"(a[2]), "r"(a[3]), "r"(b0), "r"(b1));
}

// ---------------- kernel 1: ordered compaction ----------------
__global__ void k_extract(const float* __restrict__ ef) {
    int b = blockIdx.x;
    int lane = threadIdx.x;
    const float* base = ef + (size_t)b * EF_BSTRIDE;
    int cnt = 0;
    for (int j0 = 0; j0 < NN; j0 += 32) {
        int j = j0 + lane;
        int i = j / N;
        int c = j - i * N;
        float v = base[(size_t)(1 + i) * F + H + c];
        bool act = (v > 0.5f);
        unsigned m = __ballot_sync(0xffffffffu, act);
        if (act) {
            int pos = cnt + __popc(m & ((1u << lane) - 1u));
            if (pos < KA) g_idx[b * KA + pos] = j;
        }
        cnt += __popc(m);
    }
}

// ---------------- kernel 2: base1 ----------------
__global__ void k_base1(const float* __restrict__ ef,
                        const float* __restrict__ aW1,
                        const float* __restrict__ ab1) {
    __shared__ float sg[H];
    int b = blockIdx.x;
    int o = blockIdx.y * 256 + threadIdx.x;
    if (threadIdx.x < H) sg[threadIdx.x] = ef[(size_t)b * EF_BSTRIDE + threadIdx.x];
    __syncthreads();
    float acc = ab1[o];
#pragma unroll 8
    for (int h = 0; h < H; h++) acc += sg[h] * aW1[(size_t)h * HA + o];
    g_base1[b * HA + o] = acc;
}

// ---------------- kernel 3: P1/P2 GEMM (fp32) ----------------
__global__ void __launch_bounds__(256) k_pgemm(const float* __restrict__ ef,
                                               const float* __restrict__ aW1) {
    __shared__ float As[16][68];
    __shared__ float W1s[16][64];
    __shared__ float W2s[16][64];
    int tid = threadIdx.x;
    int tx = tid & 15, ty = tid >> 4;
    int r0 = blockIdx.x * 64;
    int c0 = blockIdx.y * 64;

    float acc1[4][4], acc2[4][4];
#pragma unroll
    for (int i = 0; i < 4; i++)
#pragma unroll
        for (int j = 0; j < 4; j++) { acc1[i][j] = 0.f; acc2[i][j] = 0.f; }

    int lrow = tid >> 2;
    int lk4  = (tid & 3) * 4;
    int grow = r0 + lrow;
    int gb = grow / N;
    int gn = grow - gb * N;
    const float* aptr = ef + (size_t)gb * EF_BSTRIDE + (size_t)(1 + gn) * F;
    int wkr = tid >> 4;
    int wc4 = (tid & 15) * 4;

    for (int k0 = 0; k0 < H; k0 += 16) {
        float4 av = *(const float4*)(aptr + k0 + lk4);
        float4 w1 = *(const float4*)(aW1 + (size_t)(H + k0 + wkr) * HA + c0 + wc4);
        float4 w2 = *(const float4*)(aW1 + (size_t)(2 * H + k0 + wkr) * HA + c0 + wc4);
        As[lk4 + 0][lrow] = av.x; As[lk4 + 1][lrow] = av.y;
        As[lk4 + 2][lrow] = av.z; As[lk4 + 3][lrow] = av.w;
        *(float4*)&W1s[wkr][wc4] = w1;
        *(float4*)&W2s[wkr][wc4] = w2;
        __syncthreads();
#pragma unroll
        for (int k = 0; k < 16; k++) {
            float a[4], b1[4], b2[4];
            *(float4*)a  = *(const float4*)&As[k][ty * 4];
            *(float4*)b1 = *(const float4*)&W1s[k][tx * 4];
            *(float4*)b2 = *(const float4*)&W2s[k][tx * 4];
#pragma unroll
            for (int i = 0; i < 4; i++)
#pragma unroll
                for (int j = 0; j < 4; j++) {
                    acc1[i][j] += a[i] * b1[j];
                    acc2[i][j] += a[i] * b2[j];
                }
        }
        __syncthreads();
    }
#pragma unroll
    for (int i = 0; i < 4; i++) {
        int row = r0 + ty * 4 + i;
        float* p1 = g_P1 + (size_t)row * HA + c0 + tx * 4;
        float* p2 = g_P2 + (size_t)row * HA + c0 + tx * 4;
        *(float4*)p1 = make_float4(acc1[i][0], acc1[i][1], acc1[i][2], acc1[i][3]);
        *(float4*)p2 = make_float4(acc2[i][0], acc2[i][1], acc2[i][2], acc2[i][3]);
    }
}

// ---------------- kernel 3b: transpose aW2 -> g_W2t[n][k], tf32-rounded ----------------
__global__ void k_tw2(const float* __restrict__ aW2) {
    __shared__ float t[32][33];
    int bx = blockIdx.x * 32, by = blockIdx.y * 32;
    int x = threadIdx.x, y = threadIdx.y;  // 32 x 8
    for (int yy = y; yy < 32; yy += 8)
        t[yy][x] = aW2[(size_t)(by + yy) * HA + bx + x];
    __syncthreads();
    for (int yy = y; yy < 32; yy += 8)
        g_W2t[(size_t)(bx + yy) * HA + by + x] = to_tf32(t[x][yy]);
}

// ---------------- kernel 4: Y1 = tf32(tanh(base1 + P1[i1] + P2[i2])) ----------------
__global__ void k_y1() {
    int row = blockIdx.x;
    int b = row / KA;
    int id = g_idx[row];
    int i1 = id / N;
    int i2 = id - i1 * N;
    const float4* p1 = (const float4*)(g_P1 + (size_t)(b * N + i1) * HA);
    const float4* p2 = (const float4*)(g_P2 + (size_t)(b * N + i2) * HA);
    const float4* bs = (const float4*)(g_base1 + (size_t)b * HA);
    float4* y = (float4*)(g_Y1 + (size_t)row * HA);
    int t = threadIdx.x;
    float4 a = p1[t], c = p2[t], d = bs[t];
    float4 r;
    r.x = to_tf32(tanhf(a.x + c.x + d.x));
    r.y = to_tf32(tanhf(a.y + c.y + d.y));
    r.z = to_tf32(tanhf(a.z + c.z + d.z));
    r.w = to_tf32(tanhf(a.w + c.w + d.w));
    y[t] = r;
}

// ---------------- kernel 5: HMMA tf32 layer2 GEMM + fused layer3 ----------------
// CTA: 128 rows x (4 col-tiles of 256), K=1024. 8 warps (2 row x 4 col),
// warp tile 64x64 (mt=4, nt=8). ldmatrix fragment loads, 3-stage cp.async,
// one __syncthreads per K-slice of 16.
// smem bytes: 3 stages x (A 128x20x4 + B 256x20x4 = 30720) = 92160,
//             ab2 @92160 (4096), w3 @96256 (4096), red @100352 (2048) -> 102400.
#define L23_SMEM 102400
#define STG_B    30720
#define OFFB_B   10240
extern __shared__ __align__(16) float smf[];

__global__ void __launch_bounds__(256, 1) k_l23(const float* __restrict__ ab2,
                                                const float* __restrict__ aW3) {
    const int tid = threadIdx.x;
    const int wid = tid >> 5;
    const int lane = tid & 31;
    const int wy = wid >> 2;     // 0..1 : 64-row band
    const int wx = wid & 3;      // 0..3 : 64-col band
    const size_t r0 = (size_t)blockIdx.x * 128;

    float* sab2 = smf + 23040;
    float* sw3  = smf + 24064;
    float* sred = smf + 25088;   // [4][128]
    const uint32_t su = s2u(smf);

#pragma unroll
    for (int i = tid; i < 1024; i += 256) {
        sab2[i] = ab2[i];
        sw3[i]  = aW3[i];
    }

    const int gq = lane >> 2;
    const int gt = lane & 3;

    // ldmatrix per-lane byte offsets (stride = 20 floats = 80B per row)
    const uint32_t a_lane = (uint32_t)((lane & 7) * 80 + (lane & 8) * 80 + (lane & 16));
    const uint32_t b_lane = (uint32_t)((lane & 7) * 80 + (lane & 8) * 2 + (lane & 16) * 40);
    const uint32_t aw_off = (uint32_t)(wy * 64 * 80) + a_lane;         // + mt*1280 + k8*32
    const uint32_t bw_off = OFFB_B + (uint32_t)(wx * 64 * 80) + b_lane; // + p*1280 + k8*32

    // cp.async thread roles
    const int am = tid >> 2;            // A rows handled: am, am+64
    const int ac4 = (tid & 3) * 4;
    const uint32_t a_dst0 = (uint32_t)(am * 80 + ac4 * 4);
    const uint32_t a_dst1 = (uint32_t)((am + 64) * 80 + ac4 * 4);
    const uint32_t b_dst0 = OFFB_B + (uint32_t)(am * 80 + ac4 * 4);

    float lsum[8];
#pragma unroll
    for (int i = 0; i < 8; i++) lsum[i] = 0.f;

    const float* Abase = g_Y1 + r0 * HA;

    for (int ct = 0; ct < 4; ct++) {
        const float* Bbase = g_W2t + (size_t)(ct * 256) * HA;
        float acc[4][8][4];
#pragma unroll
        for (int mt = 0; mt < 4; mt++)
#pragma unroll
            for (int nt = 0; nt < 8; nt++)
#pragma unroll
                for (int r = 0; r < 4; r++) acc[mt][nt][r] = 0.f;

        __syncthreads();   // protect stages 0/1 from lagging readers of prev ct

        // preload kt=0,1
#pragma unroll
        for (int pk = 0; pk < 2; pk++) {
            const uint32_t sb = su + pk * STG_B;
            const int k0 = pk * 16;
            CPA16(sb + a_dst0, Abase + (size_t)am * HA + k0 + ac4);
            CPA16(sb + a_dst1, Abase + (size_t)(am + 64) * HA + k0 + ac4);
#pragma unroll
            for (int it = 0; it < 4; it++) {
                int n = am + it * 64;
                CPA16(sb + b_dst0 + (uint32_t)(it * 64 * 80),
                      Bbase + (size_t)n * HA + k0 + ac4);
            }
            CPA_COMMIT();
        }

        for (int kt = 0; kt < 64; kt++) {
            const int s = kt - (kt / 3) * 3;      // kt % 3
            if (kt < 63) { CPA_WAIT(1); } else { CPA_WAIT(0); }
            __syncthreads();

            if (kt < 62) {
                const int ktn = kt + 2;
                const int sn = ktn - (ktn / 3) * 3;
                const uint32_t sb = su + sn * STG_B;
                const int k0 = ktn * 16;
                CPA16(sb + a_dst0, Abase + (size_t)am * HA + k0 + ac4);
                CPA16(sb + a_dst1, Abase + (size_t)(am + 64) * HA + k0 + ac4);
#pragma unroll
                for (int it = 0; it < 4; it++) {
                    int n = am + it * 64;
                    CPA16(sb + b_dst0 + (uint32_t)(it * 64 * 80),
                          Bbase + (size_t)n * HA + k0 + ac4);
                }
                CPA_COMMIT();
            }

            const uint32_t sA = su + s * STG_B + aw_off;
            const uint32_t sB = su + s * STG_B + bw_off;
#pragma unroll
            for (int k8 = 0; k8 < 2; k8++) {
                uint32_t af[4][4];
#pragma unroll
                for (int mt = 0; mt < 4; mt++)
                    LDSM4(af[mt][0], af[mt][1], af[mt][2], af[mt][3],
                          sA + mt * 1280 + k8 * 32);
                uint32_t bf[4][4];
#pragma unroll
                for (int p = 0; p < 4; p++)
                    LDSM4(bf[p][0], bf[p][1], bf[p][2], bf[p][3],
                          sB + p * 1280 + k8 * 32);
#pragma unroll
                for (int mt = 0; mt < 4; mt++)
#pragma unroll
                    for (int nt = 0; nt < 8; nt++)
                        mma_tf32(acc[mt][nt], af[mt],
                                 bf[nt >> 1][(nt & 1) * 2], bf[nt >> 1][(nt & 1) * 2 + 1]);
            }
        }

        // fused layer-3 epilogue for this 256-col tile
#pragma unroll
        for (int mt = 0; mt < 4; mt++)
#pragma unroll
            for (int rr = 0; rr < 2; rr++) {
                float v = 0.f;
#pragma unroll
                for (int nt = 0; nt < 8; nt++) {
                    int col = ct * 256 + wx * 64 + nt * 8 + gt * 2;
                    float x0 = acc[mt][nt][rr * 2 + 0] + sab2[col];
                    float x1 = acc[mt][nt][rr * 2 + 1] + sab2[col + 1];
                    v += tanh_fast(x0) * sw3[col] + tanh_fast(x1) * sw3[col + 1];
                }
                lsum[mt * 2 + rr] += v;
            }
    }

    // reduce across quad lanes (cols), then across the 4 col-band warps
#pragma unroll
    for (int i = 0; i < 8; i++) {
        float v = lsum[i];
        v += __shfl_xor_sync(0xffffffffu, v, 1);
        v += __shfl_xor_sync(0xffffffffu, v, 2);
        if (gt == 0) {
            int lr = wy * 64 + (i >> 1) * 16 + (i & 1) * 8 + gq;
            sred[wx * 128 + lr] = v;
        }
    }
    __syncthreads();
    if (tid < 128) {
        float v = (sred[tid] + sred[128 + tid]) + (sred[256 + tid] + sred[384 + tid]);
        g_logits[r0 + tid] = v;
    }
}

// ---------------- kernel 6: zero ----------------
__global__ void k_zero(float* __restrict__ out) {
    int i = blockIdx.x * blockDim.x + threadIdx.x;
    if (i < OUT_FILLED) out[i] = 0.f;
}

// ---------------- kernel 7: softmax + scatter ----------------
__global__ void k_softmax(float* __restrict__ out, const float* __restrict__ ab3) {
    __shared__ float slog[KA];
    __shared__ float sred2[32];
    __shared__ float sbcast;
    int b = blockIdx.x;
    int tid = threadIdx.x;  // 1024
    float b3 = ab3[0];
    for (int k = tid; k < KA; k += 1024)
        slog[k] = g_logits[b * KA + k] + b3;
    __syncthreads();

    float m = -3.4e38f;
    for (int k = tid; k < KA; k += 1024) m = fmaxf(m, slog[k]);
#pragma unroll
    for (int o = 16; o; o >>= 1) m = fmaxf(m, __shfl_xor_sync(0xffffffffu, m, o));
    if ((tid & 31) == 0) sred2[tid >> 5] = m;
    __syncthreads();
    if (tid < 32) {
        float v = sred2[tid];
#pragma unroll
        for (int o = 16; o; o >>= 1) v = fmaxf(v, __shfl_xor_sync(0xffffffffu, v, o));
        if (tid == 0) sbcast = v;
    }
    __syncthreads();
    float gmax = sbcast;

    float s = 0.f;
    for (int k = tid; k < KA; k += 1024) s += expf(slog[k] - gmax);
#pragma unroll
    for (int o = 16; o; o >>= 1) s += __shfl_xor_sync(0xffffffffu, s, o);
    if ((tid & 31) == 0) sred2[tid >> 5] = s;
    __syncthreads();
    if (tid < 32) {
        float v = sred2[tid];
#pragma unroll
        for (int o = 16; o; o >>= 1) v += __shfl_xor_sync(0xffffffffu, v, o);
        if (tid == 0) sbcast = v;
    }
    __syncthreads();
    float inv = 1.0f / sbcast;

    for (int k = tid; k < KA; k += 1024) {
        int j = g_idx[b * KA + k];
        out[(size_t)b * NN + j] = expf(slog[k] - gmax) * inv;
    }
}

// ---------------- kernel 8: value head ----------------
__global__ void k_value(const float* __restrict__ ef,
                        const float* __restrict__ cW1, const float* __restrict__ cb1,
                        const float* __restrict__ cW2, const float* __restrict__ cb2,
                        const float* __restrict__ cW3, const float* __restrict__ cb3,
                        float* __restrict__ out) {
    __shared__ float sg[H];
    __shared__ float h1[HC];
    __shared__ float h2[HC];
    __shared__ float sr[16];
    int b = blockIdx.x;
    int tid = threadIdx.x;  // 512
    if (tid < H) sg[tid] = ef[(size_t)b * EF_BSTRIDE + tid];
    __syncthreads();
    float acc = cb1[tid];
#pragma unroll 8
    for (int h = 0; h < H; h++) acc += sg[h] * cW1[h * HC + tid];
    h1[tid] = tanhf(acc);
    __syncthreads();
    float acc2 = cb2[tid];
#pragma unroll 8
    for (int h = 0; h < HC; h++) acc2 += h1[h] * cW2[h * HC + tid];
    h2[tid] = tanhf(acc2);
    __syncthreads();
    float p = h2[tid] * cW3[tid];
#pragma unroll
    for (int o = 16; o; o >>= 1) p += __shfl_xor_sync(0xffffffffu, p, o);
    if ((tid & 31) == 0) sr[tid >> 5] = p;
    __syncthreads();
    if (tid < 16) {
        float v = sr[tid];
#pragma unroll
        for (int o = 8; o; o >>= 1) v += __shfl_xor_sync(0x0000ffffu, v, o);
        if (tid == 0) out[OUT_FILLED + b] = v + cb3[0];
    }
}

// ---------------- launch ----------------
extern "C" void kernel_launch(void* const* d_in, const int* in_sizes, int n_in,
                              void* d_out, int out_size) {
    const float* ef  = (const float*)d_in[0];
    const float* aW1 = (const float*)d_in[1];
    const float* ab1 = (const float*)d_in[2];
    const float* aW2 = (const float*)d_in[3];
    const float* ab2 = (const float*)d_in[4];
    const float* aW3 = (const float*)d_in[5];
    const float* ab3 = (const float*)d_in[6];
    const float* cW1 = (const float*)d_in[7];
    const float* cb1 = (const float*)d_in[8];
    const float* cW2 = (const float*)d_in[9];
    const float* cb2 = (const float*)d_in[10];
    const float* cW3 = (const float*)d_in[11];
    const float* cb3 = (const float*)d_in[12];
    float* out = (float*)d_out;

    cudaFuncSetAttribute(k_l23, cudaFuncAttributeMaxDynamicSharedMemorySize, L23_SMEM);

    k_extract<<<B, 32>>>(ef);
    k_base1<<<dim3(B, 4), 256>>>(ef, aW1, ab1);
    k_pgemm<<<dim3(50, 16), 256>>>(ef, aW1);
    k_tw2<<<dim3(32, 32), dim3(32, 8)>>>(aW2);
    k_y1<<<B * KA, 256>>>();
    k_l23<<<1250, 256, L23_SMEM>>>(ab2, aW3);
    k_zero<<<625, 512>>>(out);
    k_value<<<B, 512>>>(ef, cW1, cb1, cW2, cb2, cW3, cb3, out);
    k_softmax<<<B, 1024>>>(out, ab3);
}

// round 5
// speedup vs baseline: 4.8422x; 1.6460x over previous
#include <cuda_runtime.h>
#include <cuda_fp16.h>
#include <math.h>
#include <stdint.h>

#define B   32
#define N   100
#define H   256
#define HA  1024
#define HC  512
#define KA  5000
#define NN  10000
#define F   356
#define EF_BSTRIDE (101 * 356)
#define OUT_FILLED 320000

// ---------------- scratch ----------------
__device__ int    g_idx[B * KA];
__device__ float  g_base1[B * HA];
__device__ float  g_P1[B * N * HA];
__device__ float  g_P2[B * N * HA];
__device__ __half g_Y1h[(size_t)B * KA * HA];   // 327 MB fp16
__device__ __half g_W2th[HA * HA];              // aW2 transposed [n][k] fp16
__device__ float  g_logits[B * KA];

// ---------------- helpers ----------------
__device__ __forceinline__ uint32_t s2u(const void* p) {
    return (uint32_t)__cvta_generic_to_shared(p);
}
__device__ __forceinline__ float tanh_fast(float x) {
    float r;
    asm("tanh.approx.f32 %0, %1;" : "=f"(r) : "f"(x));
    return r;
}
#define CPA16(dst, src) asm volatile("cp.async.cg.shared.global [%0], [%1], 16;" :: "r"(dst), "l"(src) : "memory")
#define CPA_COMMIT()    asm volatile("cp.async.commit_group;" ::: "memory")
#define CPA_WAIT(n)     asm volatile("cp.async.wait_group %0;" :: "n"(n) : "memory")

#define LDSM4(r0, r1, r2, r3, a) \
    asm volatile("ldmatrix.sync.aligned.m8n8.x4.shared.b16 {%0,%1,%2,%3}, [%4];" \
        : "=r"(r0), "=r"(r1), "=r"(r2), "=r"(r3) : "r"(a))

__device__ __forceinline__ void mma_f16(float* c, const uint32_t* a, uint32_t b0, uint32_t b1) {
    asm volatile("mma.sync.aligned.m16n8k16.row.col.f32.f16.f16.f32 "
        "{%0,%1,%2,%3}, {%4,%5,%6,%7}, {%8,%9}, {%0,%1,%2,%3};"
        : "+f"(c[0]), "+f"(c[1]), "+f"(c[2]), "+f"(c[3])
        : "r"(a[0]), "r"(a[1]), "r"(a[2]), "r"(a[3]), "r"(b0), "r"(b1));
}

// ---------------- kernel 1: fused prep (extract | base1 | tw2->half) ----------------
__global__ void k_prep(const float* __restrict__ ef,
                       const float* __restrict__ aW1,
                       const float* __restrict__ ab1,
                       const float* __restrict__ aW2) {
    __shared__ float sg[H];
    __shared__ float tt[32][33];
    int blk = blockIdx.x;
    int tid = threadIdx.x;

    if (blk < 32) {
        // ---- extract: warp 0 only ----
        if (tid < 32) {
            int b = blk;
            int lane = tid;
            const float* base = ef + (size_t)b * EF_BSTRIDE;
            int cnt = 0;
            for (int j0 = 0; j0 < NN; j0 += 32) {
                int j = j0 + lane;
                int i = j / N;
                int c = j - i * N;
                float v = base[(size_t)(1 + i) * F + H + c];
                bool act = (v > 0.5f);
                unsigned m = __ballot_sync(0xffffffffu, act);
                if (act) {
                    int pos = cnt + __popc(m & ((1u << lane) - 1u));
                    if (pos < KA) g_idx[b * KA + pos] = j;
                }
                cnt += __popc(m);
            }
        }
    } else if (blk < 160) {
        // ---- base1 ----
        int idx = blk - 32;
        int b = idx >> 2;
        int o = (idx & 3) * 256 + tid;
        if (tid < H) sg[tid] = ef[(size_t)b * EF_BSTRIDE + tid];
        __syncthreads();
        float acc = ab1[o];
#pragma unroll 8
        for (int h = 0; h < H; h++) acc += sg[h] * aW1[(size_t)h * HA + o];
        g_base1[b * HA + o] = acc;
    } else {
        // ---- transpose aW2 -> half ----
        int bid = blk - 160;
        int bx = (bid & 31) * 32, by = (bid >> 5) * 32;
        int x = tid & 31, y = tid >> 5;   // 32 x 8
        for (int yy = y; yy < 32; yy += 8)
            tt[yy][x] = aW2[(size_t)(by + yy) * HA + bx + x];
        __syncthreads();
        for (int yy = y; yy < 32; yy += 8)
            g_W2th[(size_t)(bx + yy) * HA + by + x] = __float2half_rn(tt[x][yy]);
    }
}

// ---------------- kernel 2: P1/P2 GEMM (fp32) ----------------
__global__ void __launch_bounds__(256) k_pgemm(const float* __restrict__ ef,
                                               const float* __restrict__ aW1) {
    __shared__ float As[16][68];
    __shared__ float W1s[16][64];
    __shared__ float W2s[16][64];
    int tid = threadIdx.x;
    int tx = tid & 15, ty = tid >> 4;
    int r0 = blockIdx.x * 64;
    int c0 = blockIdx.y * 64;

    float acc1[4][4], acc2[4][4];
#pragma unroll
    for (int i = 0; i < 4; i++)
#pragma unroll
        for (int j = 0; j < 4; j++) { acc1[i][j] = 0.f; acc2[i][j] = 0.f; }

    int lrow = tid >> 2;
    int lk4  = (tid & 3) * 4;
    int grow = r0 + lrow;
    int gb = grow / N;
    int gn = grow - gb * N;
    const float* aptr = ef + (size_t)gb * EF_BSTRIDE + (size_t)(1 + gn) * F;
    int wkr = tid >> 4;
    int wc4 = (tid & 15) * 4;

    for (int k0 = 0; k0 < H; k0 += 16) {
        float4 av = *(const float4*)(aptr + k0 + lk4);
        float4 w1 = *(const float4*)(aW1 + (size_t)(H + k0 + wkr) * HA + c0 + wc4);
        float4 w2 = *(const float4*)(aW1 + (size_t)(2 * H + k0 + wkr) * HA + c0 + wc4);
        As[lk4 + 0][lrow] = av.x; As[lk4 + 1][lrow] = av.y;
        As[lk4 + 2][lrow] = av.z; As[lk4 + 3][lrow] = av.w;
        *(float4*)&W1s[wkr][wc4] = w1;
        *(float4*)&W2s[wkr][wc4] = w2;
        __syncthreads();
#pragma unroll
        for (int k = 0; k < 16; k++) {
            float a[4], b1[4], b2[4];
            *(float4*)a  = *(const float4*)&As[k][ty * 4];
            *(float4*)b1 = *(const float4*)&W1s[k][tx * 4];
            *(float4*)b2 = *(const float4*)&W2s[k][tx * 4];
#pragma unroll
            for (int i = 0; i < 4; i++)
#pragma unroll
                for (int j = 0; j < 4; j++) {
                    acc1[i][j] += a[i] * b1[j];
                    acc2[i][j] += a[i] * b2[j];
                }
        }
        __syncthreads();
    }
#pragma unroll
    for (int i = 0; i < 4; i++) {
        int row = r0 + ty * 4 + i;
        float* p1 = g_P1 + (size_t)row * HA + c0 + tx * 4;
        float* p2 = g_P2 + (size_t)row * HA + c0 + tx * 4;
        *(float4*)p1 = make_float4(acc1[i][0], acc1[i][1], acc1[i][2], acc1[i][3]);
        *(float4*)p2 = make_float4(acc2[i][0], acc2[i][1], acc2[i][2], acc2[i][3]);
    }
}

// ---------------- kernel 3: Y1h = half(tanh(base1 + P1[i1] + P2[i2])) ----------------
__global__ void k_y1() {
    int row = blockIdx.x;
    int b = row / KA;
    int id = g_idx[row];
    int i1 = id / N;
    int i2 = id - i1 * N;
    const float4* p1 = (const float4*)(g_P1 + (size_t)(b * N + i1) * HA);
    const float4* p2 = (const float4*)(g_P2 + (size_t)(b * N + i2) * HA);
    const float4* bs = (const float4*)(g_base1 + (size_t)b * HA);
    int t = threadIdx.x;   // 256 -> 4 floats each
    float4 a = p1[t], c = p2[t], d = bs[t];
    __half2 h0 = __floats2half2_rn(tanhf(a.x + c.x + d.x), tanhf(a.y + c.y + d.y));
    __half2 h1 = __floats2half2_rn(tanhf(a.z + c.z + d.z), tanhf(a.w + c.w + d.w));
    __half2* y = (__half2*)(g_Y1h + (size_t)row * HA);
    y[t * 2]     = h0;
    y[t * 2 + 1] = h1;
}

// ---------------- kernel 4: fp16 HMMA layer2 GEMM + fused layer3 ----------------
// CTA: 128 rows x (4 col-tiles of 256), K=1024, K-slice 32 per stage.
// 8 warps (2 row x 4 col), warp tile 64x64 (mt=4, nt=8), m16n8k16.
// 5 stages x 30720 B, wait(3); flattened 128-iter loop, continuous prefetch.
// smem rows: stride 80 B (32 halves data + pad) -> ldmatrix conflict-free.
#define NSTG    5
#define STG_B   30720
#define OFFB_B  10240
#define NIT     128
#define L23_SMEM (NSTG * STG_B + 10240)   // +ab2(4K) +w3(4K) +red(2K) = 163840
extern __shared__ __align__(128) float smf[];

__global__ void __launch_bounds__(256, 1) k_l23(const float* __restrict__ ab2,
                                                const float* __restrict__ aW3) {
    const int tid = threadIdx.x;
    const int wid = tid >> 5;
    const int lane = tid & 31;
    const int wy = wid >> 2;     // 0..1 : 64-row band
    const int wx = wid & 3;      // 0..3 : 64-col band
    const size_t r0 = (size_t)blockIdx.x * 128;

    float* sab2 = smf + (NSTG * STG_B) / 4;        // 1024 floats
    float* sw3  = sab2 + 1024;
    float* sred = sw3 + 1024;                      // [4][128]
    const uint32_t su = s2u(smf);

#pragma unroll
    for (int i = tid; i < 1024; i += 256) {
        sab2[i] = ab2[i];
        sw3[i]  = aW3[i];
    }

    const int gq = lane >> 2;
    const int gt = lane & 3;

    // ldmatrix lane offsets (row stride 80 B)
    const uint32_t aw_off = (uint32_t)(wy * 64 * 80)
                          + (uint32_t)((lane & 15) * 80 + ((lane & 16) >> 4) * 16);
    const uint32_t bw_off = OFFB_B + (uint32_t)(wx * 64 * 80)
                          + (uint32_t)(((lane & 7) + ((lane & 16) >> 1)) * 80 + ((lane & 8) >> 3) * 16);

    // cp.async roles: 16B chunks; A: 128 rows x 4 chunks, B: 256 rows x 4 chunks
    const __half* Ybase = g_Y1h + r0 * HA;

    auto issue_stage = [&](int p) {
        if (p < NIT) {
            const int pct = p >> 5;
            const int k0 = (p & 31) * 32;
            const uint32_t sb = su + (uint32_t)(p % NSTG) * STG_B;
            const __half* Ab = Ybase + k0;
            const __half* Bb = g_W2th + (size_t)(pct * 256) * HA + k0;
#pragma unroll
            for (int it = 0; it < 2; it++) {
                int idx = tid + it * 256;          // 0..511
                int row = idx >> 2, c = idx & 3;
                CPA16(sb + (uint32_t)(row * 80 + c * 16), Ab + (size_t)row * HA + c * 8);
            }
#pragma unroll
            for (int it = 0; it < 4; it++) {
                int idx = tid + it * 256;          // 0..1023
                int row = idx >> 2, c = idx & 3;
                CPA16(sb + OFFB_B + (uint32_t)(row * 80 + c * 16), Bb + (size_t)row * HA + c * 8);
            }
        }
        CPA_COMMIT();
    };

    float lsum[8];
#pragma unroll
    for (int i = 0; i < 8; i++) lsum[i] = 0.f;

    float acc[4][8][4];
#pragma unroll
    for (int mt = 0; mt < 4; mt++)
#pragma unroll
        for (int nt = 0; nt < 8; nt++)
#pragma unroll
            for (int r = 0; r < 4; r++) acc[mt][nt][r] = 0.f;

    // prologue: 4 stages in flight
    issue_stage(0); issue_stage(1); issue_stage(2); issue_stage(3);

    for (int it = 0; it < NIT; it++) {
        CPA_WAIT(3);
        __syncthreads();
        issue_stage(it + 4);

        const uint32_t sb = su + (uint32_t)(it % NSTG) * STG_B;
        const uint32_t sA = sb + aw_off;
        const uint32_t sB = sb + bw_off;
#pragma unroll
        for (int k16 = 0; k16 < 2; k16++) {
            uint32_t af[4][4];
#pragma unroll
            for (int mt = 0; mt < 4; mt++)
                LDSM4(af[mt][0], af[mt][1], af[mt][2], af[mt][3],
                      sA + mt * 1280 + k16 * 32);
            uint32_t bf[4][4];
#pragma unroll
            for (int p = 0; p < 4; p++)
                LDSM4(bf[p][0], bf[p][1], bf[p][2], bf[p][3],
                      sB + p * 1280 + k16 * 32);
#pragma unroll
            for (int mt = 0; mt < 4; mt++)
#pragma unroll
                for (int nt = 0; nt < 8; nt++)
                    mma_f16(acc[mt][nt], af[mt],
                            bf[nt >> 1][(nt & 1) * 2], bf[nt >> 1][(nt & 1) * 2 + 1]);
        }

        if ((it & 31) == 31) {
            const int ct = it >> 5;
            // fused layer-3 epilogue for this 256-col tile
#pragma unroll
            for (int mt = 0; mt < 4; mt++)
#pragma unroll
                for (int rr = 0; rr < 2; rr++) {
                    float v = 0.f;
#pragma unroll
                    for (int nt = 0; nt < 8; nt++) {
                        int col = ct * 256 + wx * 64 + nt * 8 + gt * 2;
                        float x0 = acc[mt][nt][rr * 2 + 0] + sab2[col];
                        float x1 = acc[mt][nt][rr * 2 + 1] + sab2[col + 1];
                        v += tanh_fast(x0) * sw3[col] + tanh_fast(x1) * sw3[col + 1];
                    }
                    lsum[mt * 2 + rr] += v;
                }
#pragma unroll
            for (int mt = 0; mt < 4; mt++)
#pragma unroll
                for (int nt = 0; nt < 8; nt++)
#pragma unroll
                    for (int r = 0; r < 4; r++) acc[mt][nt][r] = 0.f;
        }
    }

    // reduce across quad lanes (cols), then across the 4 col-band warps
#pragma unroll
    for (int i = 0; i < 8; i++) {
        float v = lsum[i];
        v += __shfl_xor_sync(0xffffffffu, v, 1);
        v += __shfl_xor_sync(0xffffffffu, v, 2);
        if (gt == 0) {
            int lr = wy * 64 + (i >> 1) * 16 + (i & 1) * 8 + gq;
            sred[wx * 128 + lr] = v;
        }
    }
    __syncthreads();
    if (tid < 128) {
        float v = (sred[tid] + sred[128 + tid]) + (sred[256 + tid] + sred[384 + tid]);
        g_logits[r0 + tid] = v;
    }
}

// ---------------- kernel 5: zero ----------------
__global__ void k_zero(float* __restrict__ out) {
    int i = blockIdx.x * blockDim.x + threadIdx.x;
    if (i < OUT_FILLED) out[i] = 0.f;
}

// ---------------- kernel 6: value head ----------------
__global__ void k_value(const float* __restrict__ ef,
                        const float* __restrict__ cW1, const float* __restrict__ cb1,
                        const float* __restrict__ cW2, const float* __restrict__ cb2,
                        const float* __restrict__ cW3, const float* __restrict__ cb3,
                        float* __restrict__ out) {
    __shared__ float sg[H];
    __shared__ float h1[HC];
    __shared__ float h2[HC];
    __shared__ float sr[16];
    int b = blockIdx.x;
    int tid = threadIdx.x;  // 512
    if (tid < H) sg[tid] = ef[(size_t)b * EF_BSTRIDE + tid];
    __syncthreads();
    float acc = cb1[tid];
#pragma unroll 8
    for (int h = 0; h < H; h++) acc += sg[h] * cW1[h * HC + tid];
    h1[tid] = tanhf(acc);
    __syncthreads();
    float acc2 = cb2[tid];
#pragma unroll 8
    for (int h = 0; h < HC; h++) acc2 += h1[h] * cW2[h * HC + tid];
    h2[tid] = tanhf(acc2);
    __syncthreads();
    float p = h2[tid] * cW3[tid];
#pragma unroll
    for (int o = 16; o; o >>= 1) p += __shfl_xor_sync(0xffffffffu, p, o);
    if ((tid & 31) == 0) sr[tid >> 5] = p;
    __syncthreads();
    if (tid < 16) {
        float v = sr[tid];
#pragma unroll
        for (int o = 8; o; o >>= 1) v += __shfl_xor_sync(0x0000ffffu, v, o);
        if (tid == 0) out[OUT_FILLED + b] = v + cb3[0];
    }
}

// ---------------- kernel 7: softmax + scatter ----------------
__global__ void k_softmax(float* __restrict__ out, const float* __restrict__ ab3) {
    __shared__ float slog[KA];
    __shared__ float sred2[32];
    __shared__ float sbcast;
    int b = blockIdx.x;
    int tid = threadIdx.x;  // 1024
    float b3 = ab3[0];
    for (int k = tid; k < KA; k += 1024)
        slog[k] = g_logits[b * KA + k] + b3;
    __syncthreads();

    float m = -3.4e38f;
    for (int k = tid; k < KA; k += 1024) m = fmaxf(m, slog[k]);
#pragma unroll
    for (int o = 16; o; o >>= 1) m = fmaxf(m, __shfl_xor_sync(0xffffffffu, m, o));
    if ((tid & 31) == 0) sred2[tid >> 5] = m;
    __syncthreads();
    if (tid < 32) {
        float v = sred2[tid];
#pragma unroll
        for (int o = 16; o; o >>= 1) v = fmaxf(v, __shfl_xor_sync(0xffffffffu, v, o));
        if (tid == 0) sbcast = v;
    }
    __syncthreads();
    float gmax = sbcast;

    float s = 0.f;
    for (int k = tid; k < KA; k += 1024) s += expf(slog[k] - gmax);
#pragma unroll
    for (int o = 16; o; o >>= 1) s += __shfl_xor_sync(0xffffffffu, s, o);
    if ((tid & 31) == 0) sred2[tid >> 5] = s;
    __syncthreads();
    if (tid < 32) {
        float v = sred2[tid];
#pragma unroll
        for (int o = 16; o; o >>= 1) v += __shfl_xor_sync(0xffffffffu, v, o);
        if (tid == 0) sbcast = v;
    }
    __syncthreads();
    float inv = 1.0f / sbcast;

    for (int k = tid; k < KA; k += 1024) {
        int j = g_idx[b * KA + k];
        out[(size_t)b * NN + j] = expf(slog[k] - gmax) * inv;
    }
}

// ---------------- launch ----------------
extern "C" void kernel_launch(void* const* d_in, const int* in_sizes, int n_in,
                              void* d_out, int out_size) {
    const float* ef  = (const float*)d_in[0];
    const float* aW1 = (const float*)d_in[1];
    const float* ab1 = (const float*)d_in[2];
    const float* aW2 = (const float*)d_in[3];
    const float* ab2 = (const float*)d_in[4];
    const float* aW3 = (const float*)d_in[5];
    const float* ab3 = (const float*)d_in[6];
    const float* cW1 = (const float*)d_in[7];
    const float* cb1 = (const float*)d_in[8];
    const float* cW2 = (const float*)d_in[9];
    const float* cb2 = (const float*)d_in[10];
    const float* cW3 = (const float*)d_in[11];
    const float* cb3 = (const float*)d_in[12];
    float* out = (float*)d_out;

    cudaFuncSetAttribute(k_l23, cudaFuncAttributeMaxDynamicSharedMemorySize, L23_SMEM);

    k_prep<<<1184, 256>>>(ef, aW1, ab1, aW2);           // launch 1
    k_pgemm<<<dim3(50, 16), 256>>>(ef, aW1);            // launch 2
    k_y1<<<B * KA, 256>>>();                            // launch 3
    k_l23<<<1250, 256, L23_SMEM>>>(ab2, aW3);           // launch 4 (ncu capture)
    k_zero<<<625, 512>>>(out);
    k_value<<<B, 512>>>(ef, cW1, cb1, cW2, cb2, cW3, cb3, out);
    k_softmax<<<B, 1024>>>(out, ab3);
}

// round 6
// speedup vs baseline: 5.0040x; 1.0334x over previous
#include <cuda_runtime.h>
#include <cuda_fp16.h>
#include <math.h>
#include <stdint.h>

#define B   32
#define N   100
#define H   256
#define HA  1024
#define HC  512
#define KA  5000
#define NN  10000
#define F   356
#define EF_BSTRIDE (101 * 356)
#define OUT_FILLED 320000

// ---------------- scratch ----------------
__device__ int    g_idx[B * KA];
__device__ float  g_base1[B * HA];
__device__ float  g_P1[B * N * HA];
__device__ float  g_P2[B * N * HA];
__device__ __half g_Y1h[(size_t)B * KA * HA];   // 327 MB fp16
__device__ __half g_W2th[HA * HA];              // aW2 transposed [n][k] fp16
__device__ float  g_logits[B * KA];

// ---------------- helpers ----------------
__device__ __forceinline__ uint32_t s2u(const void* p) {
    return (uint32_t)__cvta_generic_to_shared(p);
}
__device__ __forceinline__ float tanh_fast(float x) {
    float r;
    asm("tanh.approx.f32 %0, %1;" : "=f"(r) : "f"(x));
    return r;
}
#define CPA16(dst, src) asm volatile("cp.async.cg.shared.global [%0], [%1], 16;" :: "r"(dst), "l"(src) : "memory")
#define CPA_COMMIT()    asm volatile("cp.async.commit_group;" ::: "memory")
#define CPA_WAIT(n)     asm volatile("cp.async.wait_group %0;" :: "n"(n) : "memory")

#define LDSM4(r0, r1, r2, r3, a) \
    asm volatile("ldmatrix.sync.aligned.m8n8.x4.shared.b16 {%0,%1,%2,%3}, [%4];" \
        : "=r"(r0), "=r"(r1), "=r"(r2), "=r"(r3) : "r"(a))

__device__ __forceinline__ void mma_f16(float* c, const uint32_t* a, uint32_t b0, uint32_t b1) {
    asm volatile("mma.sync.aligned.m16n8k16.row.col.f32.f16.f16.f32 "
        "{%0,%1,%2,%3}, {%4,%5,%6,%7}, {%8,%9}, {%0,%1,%2,%3};"
        : "+f"(c[0]), "+f"(c[1]), "+f"(c[2]), "+f"(c[3])
        : "r"(a[0]), "r"(a[1]), "r"(a[2]), "r"(a[3]), "r"(b0), "r"(b1));
}

// ---------------- kernel 1: fused prep (extract | base1 | tw2->half) ----------------
__global__ void k_prep(const float* __restrict__ ef,
                       const float* __restrict__ aW1,
                       const float* __restrict__ ab1,
                       const float* __restrict__ aW2) {
    __shared__ float sg[H];
    __shared__ float tt[32][33];
    int blk = blockIdx.x;
    int tid = threadIdx.x;

    if (blk < 32) {
        if (tid < 32) {
            int b = blk;
            int lane = tid;
            const float* base = ef + (size_t)b * EF_BSTRIDE;
            int cnt = 0;
            for (int j0 = 0; j0 < NN; j0 += 32) {
                int j = j0 + lane;
                int i = j / N;
                int c = j - i * N;
                float v = base[(size_t)(1 + i) * F + H + c];
                bool act = (v > 0.5f);
                unsigned m = __ballot_sync(0xffffffffu, act);
                if (act) {
                    int pos = cnt + __popc(m & ((1u << lane) - 1u));
                    if (pos < KA) g_idx[b * KA + pos] = j;
                }
                cnt += __popc(m);
            }
        }
    } else if (blk < 160) {
        int idx = blk - 32;
        int b = idx >> 2;
        int o = (idx & 3) * 256 + tid;
        if (tid < H) sg[tid] = ef[(size_t)b * EF_BSTRIDE + tid];
        __syncthreads();
        float acc = ab1[o];
#pragma unroll 8
        for (int h = 0; h < H; h++) acc += sg[h] * aW1[(size_t)h * HA + o];
        g_base1[b * HA + o] = acc;
    } else {
        int bid = blk - 160;
        int bx = (bid & 31) * 32, by = (bid >> 5) * 32;
        int x = tid & 31, y = tid >> 5;   // 32 x 8
        for (int yy = y; yy < 32; yy += 8)
            tt[yy][x] = aW2[(size_t)(by + yy) * HA + bx + x];
        __syncthreads();
        for (int yy = y; yy < 32; yy += 8)
            g_W2th[(size_t)(bx + yy) * HA + by + x] = __float2half_rn(tt[x][yy]);
    }
}

// ---------------- kernel 2: P1/P2 GEMM (fp32) ----------------
__global__ void __launch_bounds__(256) k_pgemm(const float* __restrict__ ef,
                                               const float* __restrict__ aW1) {
    __shared__ float As[16][68];
    __shared__ float W1s[16][64];
    __shared__ float W2s[16][64];
    int tid = threadIdx.x;
    int tx = tid & 15, ty = tid >> 4;
    int r0 = blockIdx.x * 64;
    int c0 = blockIdx.y * 64;

    float acc1[4][4], acc2[4][4];
#pragma unroll
    for (int i = 0; i < 4; i++)
#pragma unroll
        for (int j = 0; j < 4; j++) { acc1[i][j] = 0.f; acc2[i][j] = 0.f; }

    int lrow = tid >> 2;
    int lk4  = (tid & 3) * 4;
    int grow = r0 + lrow;
    int gb = grow / N;
    int gn = grow - gb * N;
    const float* aptr = ef + (size_t)gb * EF_BSTRIDE + (size_t)(1 + gn) * F;
    int wkr = tid >> 4;
    int wc4 = (tid & 15) * 4;

    for (int k0 = 0; k0 < H; k0 += 16) {
        float4 av = *(const float4*)(aptr + k0 + lk4);
        float4 w1 = *(const float4*)(aW1 + (size_t)(H + k0 + wkr) * HA + c0 + wc4);
        float4 w2 = *(const float4*)(aW1 + (size_t)(2 * H + k0 + wkr) * HA + c0 + wc4);
        As[lk4 + 0][lrow] = av.x; As[lk4 + 1][lrow] = av.y;
        As[lk4 + 2][lrow] = av.z; As[lk4 + 3][lrow] = av.w;
        *(float4*)&W1s[wkr][wc4] = w1;
        *(float4*)&W2s[wkr][wc4] = w2;
        __syncthreads();
#pragma unroll
        for (int k = 0; k < 16; k++) {
            float a[4], b1[4], b2[4];
            *(float4*)a  = *(const float4*)&As[k][ty * 4];
            *(float4*)b1 = *(const float4*)&W1s[k][tx * 4];
            *(float4*)b2 = *(const float4*)&W2s[k][tx * 4];
#pragma unroll
            for (int i = 0; i < 4; i++)
#pragma unroll
                for (int j = 0; j < 4; j++) {
                    acc1[i][j] += a[i] * b1[j];
                    acc2[i][j] += a[i] * b2[j];
                }
        }
        __syncthreads();
    }
#pragma unroll
    for (int i = 0; i < 4; i++) {
        int row = r0 + ty * 4 + i;
        float* p1 = g_P1 + (size_t)row * HA + c0 + tx * 4;
        float* p2 = g_P2 + (size_t)row * HA + c0 + tx * 4;
        *(float4*)p1 = make_float4(acc1[i][0], acc1[i][1], acc1[i][2], acc1[i][3]);
        *(float4*)p2 = make_float4(acc2[i][0], acc2[i][1], acc2[i][2], acc2[i][3]);
    }
}

// ---------------- kernel 3: Y1h = half(tanh(base1 + P1[i1] + P2[i2])) ----------------
__global__ void k_y1() {
    int row = blockIdx.x;
    int b = row / KA;
    int id = g_idx[row];
    int i1 = id / N;
    int i2 = id - i1 * N;
    const float4* p1 = (const float4*)(g_P1 + (size_t)(b * N + i1) * HA);
    const float4* p2 = (const float4*)(g_P2 + (size_t)(b * N + i2) * HA);
    const float4* bs = (const float4*)(g_base1 + (size_t)b * HA);
    int t = threadIdx.x;
    float4 a = p1[t], c = p2[t], d = bs[t];
    __half2 h0 = __floats2half2_rn(tanhf(a.x + c.x + d.x), tanhf(a.y + c.y + d.y));
    __half2 h1 = __floats2half2_rn(tanhf(a.z + c.z + d.z), tanhf(a.w + c.w + d.w));
    __half2* y = (__half2*)(g_Y1h + (size_t)row * HA);
    y[t * 2]     = h0;
    y[t * 2 + 1] = h1;
}

// ---------------- kernel 4: fp16 HMMA layer2 GEMM + fused layer3 ----------------
// CTA: 512 threads, 16 warps (4 row-bands x 4 col-bands), tile 128x256.
// Warp tile 32x64 (mt=2, nt=8) -> 64 acc regs/thread, 4 warps/SMSP.
// K=1024 as 32 slices of 32; 5-stage cp.async, wait(3); flattened 128-iter loop.
#define NSTG    5
#define STG_B   30720
#define OFFB_B  10240
#define NIT     128
#define L23_SMEM (NSTG * STG_B + 10240)   // 163840
extern __shared__ __align__(128) float smf[];

__global__ void __launch_bounds__(512, 1) k_l23(const float* __restrict__ ab2,
                                                const float* __restrict__ aW3) {
    const int tid = threadIdx.x;
    const int wid = tid >> 5;
    const int lane = tid & 31;
    const int wy = wid >> 2;     // 0..3 : 32-row band
    const int wx = wid & 3;      // 0..3 : 64-col band
    const size_t r0 = (size_t)blockIdx.x * 128;

    float* sab2 = smf + (NSTG * STG_B) / 4;
    float* sw3  = sab2 + 1024;
    float* sred = sw3 + 1024;                      // [4][128]
    const uint32_t su = s2u(smf);

#pragma unroll
    for (int i = tid; i < 1024; i += 512) {
        sab2[i] = ab2[i];
        sw3[i]  = aW3[i];
    }

    const int gq = lane >> 2;
    const int gt = lane & 3;

    // ldmatrix lane offsets (row stride 80 B)
    const uint32_t aw_off = (uint32_t)(wy * 32 * 80)
                          + (uint32_t)((lane & 15) * 80 + ((lane & 16) >> 4) * 16);
    const uint32_t bw_off = OFFB_B + (uint32_t)(wx * 64 * 80)
                          + (uint32_t)(((lane & 7) + ((lane & 16) >> 1)) * 80 + ((lane & 8) >> 3) * 16);

    const __half* Ybase = g_Y1h + r0 * HA;

    auto issue_stage = [&](int p) {
        if (p < NIT) {
            const int pct = p >> 5;
            const int k0 = (p & 31) * 32;
            const uint32_t sb = su + (uint32_t)(p % NSTG) * STG_B;
            const __half* Ab = Ybase + k0;
            const __half* Bb = g_W2th + (size_t)(pct * 256) * HA + k0;
            {
                int row = tid >> 2, c = tid & 3;              // 128 rows x 4 chunks
                CPA16(sb + (uint32_t)(row * 80 + c * 16), Ab + (size_t)row * HA + c * 8);
            }
#pragma unroll
            for (int it = 0; it < 2; it++) {
                int idx = tid + it * 512;                     // 256 rows x 4 chunks
                int row = idx >> 2, c = idx & 3;
                CPA16(sb + OFFB_B + (uint32_t)(row * 80 + c * 16), Bb + (size_t)row * HA + c * 8);
            }
        }
        CPA_COMMIT();
    };

    float lsum[4];
#pragma unroll
    for (int i = 0; i < 4; i++) lsum[i] = 0.f;

    float acc[2][8][4];
#pragma unroll
    for (int mt = 0; mt < 2; mt++)
#pragma unroll
        for (int nt = 0; nt < 8; nt++)
#pragma unroll
            for (int r = 0; r < 4; r++) acc[mt][nt][r] = 0.f;

    issue_stage(0); issue_stage(1); issue_stage(2); issue_stage(3);

    for (int it = 0; it < NIT; it++) {
        CPA_WAIT(3);
        __syncthreads();
        issue_stage(it + 4);

        const uint32_t sb = su + (uint32_t)(it % NSTG) * STG_B;
        const uint32_t sA = sb + aw_off;
        const uint32_t sB = sb + bw_off;
#pragma unroll
        for (int k16 = 0; k16 < 2; k16++) {
            uint32_t af[2][4];
#pragma unroll
            for (int mt = 0; mt < 2; mt++)
                LDSM4(af[mt][0], af[mt][1], af[mt][2], af[mt][3],
                      sA + mt * 1280 + k16 * 32);
            uint32_t bf[4][4];
#pragma unroll
            for (int p = 0; p < 4; p++)
                LDSM4(bf[p][0], bf[p][1], bf[p][2], bf[p][3],
                      sB + p * 1280 + k16 * 32);
#pragma unroll
            for (int mt = 0; mt < 2; mt++)
#pragma unroll
                for (int nt = 0; nt < 8; nt++)
                    mma_f16(acc[mt][nt], af[mt],
                            bf[nt >> 1][(nt & 1) * 2], bf[nt >> 1][(nt & 1) * 2 + 1]);
        }

        if ((it & 31) == 31) {
            const int ct = it >> 5;
#pragma unroll
            for (int mt = 0; mt < 2; mt++)
#pragma unroll
                for (int rr = 0; rr < 2; rr++) {
                    float v = 0.f;
#pragma unroll
                    for (int nt = 0; nt < 8; nt++) {
                        int col = ct * 256 + wx * 64 + nt * 8 + gt * 2;
                        float x0 = acc[mt][nt][rr * 2 + 0] + sab2[col];
                        float x1 = acc[mt][nt][rr * 2 + 1] + sab2[col + 1];
                        v += tanh_fast(x0) * sw3[col] + tanh_fast(x1) * sw3[col + 1];
                    }
                    lsum[mt * 2 + rr] += v;
                }
#pragma unroll
            for (int mt = 0; mt < 2; mt++)
#pragma unroll
                for (int nt = 0; nt < 8; nt++)
#pragma unroll
                    for (int r = 0; r < 4; r++) acc[mt][nt][r] = 0.f;
        }
    }

    // reduce across quad lanes (cols), then across the 4 col-band warps
#pragma unroll
    for (int i = 0; i < 4; i++) {
        float v = lsum[i];
        v += __shfl_xor_sync(0xffffffffu, v, 1);
        v += __shfl_xor_sync(0xffffffffu, v, 2);
        if (gt == 0) {
            int lr = wy * 32 + (i >> 1) * 16 + (i & 1) * 8 + gq;
            sred[wx * 128 + lr] = v;
        }
    }
    __syncthreads();
    if (tid < 128) {
        float v = (sred[tid] + sred[128 + tid]) + (sred[256 + tid] + sred[384 + tid]);
        g_logits[r0 + tid] = v;
    }
}

// ---------------- kernel 5: zero ----------------
__global__ void k_zero(float* __restrict__ out) {
    int i = blockIdx.x * blockDim.x + threadIdx.x;
    if (i < OUT_FILLED) out[i] = 0.f;
}

// ---------------- kernel 6: value head ----------------
__global__ void k_value(const float* __restrict__ ef,
                        const float* __restrict__ cW1, const float* __restrict__ cb1,
                        const float* __restrict__ cW2, const float* __restrict__ cb2,
                        const float* __restrict__ cW3, const float* __restrict__ cb3,
                        float* __restrict__ out) {
    __shared__ float sg[H];
    __shared__ float h1[HC];
    __shared__ float h2[HC];
    __shared__ float sr[16];
    int b = blockIdx.x;
    int tid = threadIdx.x;  // 512
    if (tid < H) sg[tid] = ef[(size_t)b * EF_BSTRIDE + tid];
    __syncthreads();
    float acc = cb1[tid];
#pragma unroll 8
    for (int h = 0; h < H; h++) acc += sg[h] * cW1[h * HC + tid];
    h1[tid] = tanhf(acc);
    __syncthreads();
    float acc2 = cb2[tid];
#pragma unroll 8
    for (int h = 0; h < HC; h++) acc2 += h1[h] * cW2[h * HC + tid];
    h2[tid] = tanhf(acc2);
    __syncthreads();
    float p = h2[tid] * cW3[tid];
#pragma unroll
    for (int o = 16; o; o >>= 1) p += __shfl_xor_sync(0xffffffffu, p, o);
    if ((tid & 31) == 0) sr[tid >> 5] = p;
    __syncthreads();
    if (tid < 16) {
        float v = sr[tid];
#pragma unroll
        for (int o = 8; o; o >>= 1) v += __shfl_xor_sync(0x0000ffffu, v, o);
        if (tid == 0) out[OUT_FILLED + b] = v + cb3[0];
    }
}

// ---------------- kernel 7: softmax + scatter ----------------
__global__ void k_softmax(float* __restrict__ out, const float* __restrict__ ab3) {
    __shared__ float slog[KA];
    __shared__ float sred2[32];
    __shared__ float sbcast;
    int b = blockIdx.x;
    int tid = threadIdx.x;  // 1024
    float b3 = ab3[0];
    for (int k = tid; k < KA; k += 1024)
        slog[k] = g_logits[b * KA + k] + b3;
    __syncthreads();

    float m = -3.4e38f;
    for (int k = tid; k < KA; k += 1024) m = fmaxf(m, slog[k]);
#pragma unroll
    for (int o = 16; o; o >>= 1) m = fmaxf(m, __shfl_xor_sync(0xffffffffu, m, o));
    if ((tid & 31) == 0) sred2[tid >> 5] = m;
    __syncthreads();
    if (tid < 32) {
        float v = sred2[tid];
#pragma unroll
        for (int o = 16; o; o >>= 1) v = fmaxf(v, __shfl_xor_sync(0xffffffffu, v, o));
        if (tid == 0) sbcast = v;
    }
    __syncthreads();
    float gmax = sbcast;

    float s = 0.f;
    for (int k = tid; k < KA; k += 1024) s += expf(slog[k] - gmax);
#pragma unroll
    for (int o = 16; o; o >>= 1) s += __shfl_xor_sync(0xffffffffu, s, o);
    if ((tid & 31) == 0) sred2[tid >> 5] = s;
    __syncthreads();
    if (tid < 32) {
        float v = sred2[tid];
#pragma unroll
        for (int o = 16; o; o >>= 1) v += __shfl_xor_sync(0xffffffffu, v, o);
        if (tid == 0) sbcast = v;
    }
    __syncthreads();
    float inv = 1.0f / sbcast;

    for (int k = tid; k < KA; k += 1024) {
        int j = g_idx[b * KA + k];
        out[(size_t)b * NN + j] = expf(slog[k] - gmax) * inv;
    }
}

// ---------------- launch ----------------
extern "C" void kernel_launch(void* const* d_in, const int* in_sizes, int n_in,
                              void* d_out, int out_size) {
    const float* ef  = (const float*)d_in[0];
    const float* aW1 = (const float*)d_in[1];
    const float* ab1 = (const float*)d_in[2];
    const float* aW2 = (const float*)d_in[3];
    const float* ab2 = (const float*)d_in[4];
    const float* aW3 = (const float*)d_in[5];
    const float* ab3 = (const float*)d_in[6];
    const float* cW1 = (const float*)d_in[7];
    const float* cb1 = (const float*)d_in[8];
    const float* cW2 = (const float*)d_in[9];
    const float* cb2 = (const float*)d_in[10];
    const float* cW3 = (const float*)d_in[11];
    const float* cb3 = (const float*)d_in[12];
    float* out = (float*)d_out;

    cudaFuncSetAttribute(k_l23, cudaFuncAttributeMaxDynamicSharedMemorySize, L23_SMEM);

    k_prep<<<1184, 256>>>(ef, aW1, ab1, aW2);           // launch 1
    k_pgemm<<<dim3(50, 16), 256>>>(ef, aW1);            // launch 2
    k_y1<<<B * KA, 256>>>();                            // launch 3
    k_l23<<<1250, 512, L23_SMEM>>>(ab2, aW3);           // launch 4 (ncu capture)
    k_zero<<<625, 512>>>(out);
    k_value<<<B, 512>>>(ef, cW1, cb1, cW2, cb2, cW3, cb3, out);
    k_softmax<<<B, 1024>>>(out, ab3);
}

// round 7
// speedup vs baseline: 5.6979x; 1.1387x over previous
#include <cuda_runtime.h>
#include <cuda_fp16.h>
#include <math.h>
#include <stdint.h>

#define B   32
#define N   100
#define H   256
#define HA  1024
#define HC  512
#define KA  5000
#define NN  10000
#define F   356
#define EF_BSTRIDE (101 * 356)
#define OUT_FILLED 320000

// ---------------- scratch ----------------
__device__ int    g_idx[B * KA];
__device__ float  g_base1[B * HA];
__device__ float  g_P1[B * N * HA];
__device__ float  g_P2[B * N * HA];
__device__ __half g_Y1h[(size_t)B * KA * HA];   // 327 MB fp16
__device__ __half g_W2th[HA * HA];              // aW2 transposed [n][k] fp16
__device__ float  g_logits[B * KA];

// ---------------- helpers ----------------
__device__ __forceinline__ uint32_t s2u(const void* p) {
    return (uint32_t)__cvta_generic_to_shared(p);
}
__device__ __forceinline__ float tanh_fast(float x) {
    float r;
    asm("tanh.approx.f32 %0, %1;" : "=f"(r) : "f"(x));
    return r;
}
#define CPA16(dst, src) asm volatile("cp.async.cg.shared.global [%0], [%1], 16;" :: "r"(dst), "l"(src) : "memory")
#define CPA_COMMIT()    asm volatile("cp.async.commit_group;" ::: "memory")
#define CPA_WAIT(n)     asm volatile("cp.async.wait_group %0;" :: "n"(n) : "memory")

#define LDSM4(r0, r1, r2, r3, a) \
    asm volatile("ldmatrix.sync.aligned.m8n8.x4.shared.b16 {%0,%1,%2,%3}, [%4];" \
        : "=r"(r0), "=r"(r1), "=r"(r2), "=r"(r3) : "r"(a))

__device__ __forceinline__ void mma_f16(float* c, const uint32_t* a, uint32_t b0, uint32_t b1) {
    asm volatile("mma.sync.aligned.m16n8k16.row.col.f32.f16.f16.f32 "
        "{%0,%1,%2,%3}, {%4,%5,%6,%7}, {%8,%9}, {%0,%1,%2,%3};"
        : "+f"(c[0]), "+f"(c[1]), "+f"(c[2]), "+f"(c[3])
        : "r"(a[0]), "r"(a[1]), "r"(a[2]), "r"(a[3]), "r"(b0), "r"(b1));
}

// ---------------- kernel 1: fused prep (extract | base1 | tw2->half) ----------------
__global__ void k_prep(const float* __restrict__ ef,
                       const float* __restrict__ aW1,
                       const float* __restrict__ ab1,
                       const float* __restrict__ aW2) {
    __shared__ float sg[H];
    __shared__ float tt[32][33];
    int blk = blockIdx.x;
    int tid = threadIdx.x;

    if (blk < 32) {
        if (tid < 32) {
            int b = blk;
            int lane = tid;
            const float* base = ef + (size_t)b * EF_BSTRIDE;
            int cnt = 0;
            for (int j0 = 0; j0 < NN; j0 += 32) {
                int j = j0 + lane;
                int i = j / N;
                int c = j - i * N;
                float v = base[(size_t)(1 + i) * F + H + c];
                bool act = (v > 0.5f);
                unsigned m = __ballot_sync(0xffffffffu, act);
                if (act) {
                    int pos = cnt + __popc(m & ((1u << lane) - 1u));
                    if (pos < KA) g_idx[b * KA + pos] = j;
                }
                cnt += __popc(m);
            }
        }
    } else if (blk < 160) {
        int idx = blk - 32;
        int b = idx >> 2;
        int o = (idx & 3) * 256 + tid;
        if (tid < H) sg[tid] = ef[(size_t)b * EF_BSTRIDE + tid];
        __syncthreads();
        float acc = ab1[o];
#pragma unroll 8
        for (int h = 0; h < H; h++) acc += sg[h] * aW1[(size_t)h * HA + o];
        g_base1[b * HA + o] = acc;
    } else {
        int bid = blk - 160;
        int bx = (bid & 31) * 32, by = (bid >> 5) * 32;
        int x = tid & 31, y = tid >> 5;   // 32 x 8
        for (int yy = y; yy < 32; yy += 8)
            tt[yy][x] = aW2[(size_t)(by + yy) * HA + bx + x];
        __syncthreads();
        for (int yy = y; yy < 32; yy += 8)
            g_W2th[(size_t)(bx + yy) * HA + by + x] = __float2half_rn(tt[x][yy]);
    }
}

// ---------------- kernel 2: P1/P2 GEMM (fp32) ----------------
__global__ void __launch_bounds__(256) k_pgemm(const float* __restrict__ ef,
                                               const float* __restrict__ aW1) {
    __shared__ float As[16][68];
    __shared__ float W1s[16][64];
    __shared__ float W2s[16][64];
    int tid = threadIdx.x;
    int tx = tid & 15, ty = tid >> 4;
    int r0 = blockIdx.x * 64;
    int c0 = blockIdx.y * 64;

    float acc1[4][4], acc2[4][4];
#pragma unroll
    for (int i = 0; i < 4; i++)
#pragma unroll
        for (int j = 0; j < 4; j++) { acc1[i][j] = 0.f; acc2[i][j] = 0.f; }

    int lrow = tid >> 2;
    int lk4  = (tid & 3) * 4;
    int grow = r0 + lrow;
    int gb = grow / N;
    int gn = grow - gb * N;
    const float* aptr = ef + (size_t)gb * EF_BSTRIDE + (size_t)(1 + gn) * F;
    int wkr = tid >> 4;
    int wc4 = (tid & 15) * 4;

    for (int k0 = 0; k0 < H; k0 += 16) {
        float4 av = *(const float4*)(aptr + k0 + lk4);
        float4 w1 = *(const float4*)(aW1 + (size_t)(H + k0 + wkr) * HA + c0 + wc4);
        float4 w2 = *(const float4*)(aW1 + (size_t)(2 * H + k0 + wkr) * HA + c0 + wc4);
        As[lk4 + 0][lrow] = av.x; As[lk4 + 1][lrow] = av.y;
        As[lk4 + 2][lrow] = av.z; As[lk4 + 3][lrow] = av.w;
        *(float4*)&W1s[wkr][wc4] = w1;
        *(float4*)&W2s[wkr][wc4] = w2;
        __syncthreads();
#pragma unroll
        for (int k = 0; k < 16; k++) {
            float a[4], b1[4], b2[4];
            *(float4*)a  = *(const float4*)&As[k][ty * 4];
            *(float4*)b1 = *(const float4*)&W1s[k][tx * 4];
            *(float4*)b2 = *(const float4*)&W2s[k][tx * 4];
#pragma unroll
            for (int i = 0; i < 4; i++)
#pragma unroll
                for (int j = 0; j < 4; j++) {
                    acc1[i][j] += a[i] * b1[j];
                    acc2[i][j] += a[i] * b2[j];
                }
        }
        __syncthreads();
    }
#pragma unroll
    for (int i = 0; i < 4; i++) {
        int row = r0 + ty * 4 + i;
        float* p1 = g_P1 + (size_t)row * HA + c0 + tx * 4;
        float* p2 = g_P2 + (size_t)row * HA + c0 + tx * 4;
        *(float4*)p1 = make_float4(acc1[i][0], acc1[i][1], acc1[i][2], acc1[i][3]);
        *(float4*)p2 = make_float4(acc2[i][0], acc2[i][1], acc2[i][2], acc2[i][3]);
    }
}

// ---------------- kernel 3: Y1h = half(tanh(base1 + P1[i1] + P2[i2])) ----------------
__global__ void k_y1() {
    int row = blockIdx.x;
    int b = row / KA;
    int id = g_idx[row];
    int i1 = id / N;
    int i2 = id - i1 * N;
    const float4* p1 = (const float4*)(g_P1 + (size_t)(b * N + i1) * HA);
    const float4* p2 = (const float4*)(g_P2 + (size_t)(b * N + i2) * HA);
    const float4* bs = (const float4*)(g_base1 + (size_t)b * HA);
    int t = threadIdx.x;
    float4 a = p1[t], c = p2[t], d = bs[t];
    __half2 h0 = __floats2half2_rn(tanhf(a.x + c.x + d.x), tanhf(a.y + c.y + d.y));
    __half2 h1 = __floats2half2_rn(tanhf(a.z + c.z + d.z), tanhf(a.w + c.w + d.w));
    __half2* y = (__half2*)(g_Y1h + (size_t)row * HA);
    y[t * 2]     = h0;
    y[t * 2 + 1] = h1;
}

// ---------------- kernel 4: fp16 HMMA layer2 GEMM + fused layer3 ----------------
// CTA: 256 threads, 8 warps (2 row-bands x 4 col-bands), tile 128x128.
// Warp tile 64x32 (mt=4, nt=4) -> 64 acc regs. TWO CTAs per SM (independent
// barrier domains) so one CTA's wait/sync overlaps the other's MMA issue.
// K=1024 as 32 slices of 32 per col-tile; 8 col-tiles -> 256 iterations.
// 5-stage cp.async, wait(3). Stage = A(10240) + B(10240) = 20480 B.
#define NSTG    5
#define STG_B   20480
#define OFFB_B  10240
#define NIT     256
#define L23_SMEM (NSTG * STG_B + 10240)   // 112640 per CTA; x2 = 225280 <= 228KB
extern __shared__ __align__(128) float smf[];

__global__ void __launch_bounds__(256, 2) k_l23(const float* __restrict__ ab2,
                                                const float* __restrict__ aW3) {
    const int tid = threadIdx.x;
    const int wid = tid >> 5;
    const int lane = tid & 31;
    const int wy = wid >> 2;     // 0..1 : 64-row band
    const int wx = wid & 3;      // 0..3 : 32-col band
    const size_t r0 = (size_t)blockIdx.x * 128;

    float* sab2 = smf + (NSTG * STG_B) / 4;        // 1024 floats
    float* sw3  = sab2 + 1024;
    float* sred = sw3 + 1024;                      // [4][128]
    const uint32_t su = s2u(smf);

#pragma unroll
    for (int i = tid; i < 1024; i += 256) {
        sab2[i] = ab2[i];
        sw3[i]  = aW3[i];
    }

    const int gq = lane >> 2;
    const int gt = lane & 3;

    // ldmatrix lane offsets (row stride 80 B)
    const uint32_t aw_off = (uint32_t)(wy * 64 * 80)
                          + (uint32_t)((lane & 15) * 80 + ((lane & 16) >> 4) * 16);
    const uint32_t bw_off = OFFB_B + (uint32_t)(wx * 32 * 80)
                          + (uint32_t)(((lane & 7) + ((lane & 16) >> 1)) * 80 + ((lane & 8) >> 3) * 16);

    const __half* Ybase = g_Y1h + r0 * HA;

    auto issue_stage = [&](int p) {
        if (p < NIT) {
            const int pct = p >> 5;                // col tile 0..7
            const int k0 = (p & 31) * 32;
            const uint32_t sb = su + (uint32_t)(p % NSTG) * STG_B;
            const __half* Ab = Ybase + k0;
            const __half* Bb = g_W2th + (size_t)(pct * 128) * HA + k0;
#pragma unroll
            for (int it = 0; it < 2; it++) {
                int idx = tid + it * 256;          // 128 rows x 4 chunks
                int row = idx >> 2, c = idx & 3;
                CPA16(sb + (uint32_t)(row * 80 + c * 16), Ab + (size_t)row * HA + c * 8);
                CPA16(sb + OFFB_B + (uint32_t)(row * 80 + c * 16), Bb + (size_t)row * HA + c * 8);
            }
        }
        CPA_COMMIT();
    };

    float lsum[8];
#pragma unroll
    for (int i = 0; i < 8; i++) lsum[i] = 0.f;

    float acc[4][4][4];
#pragma unroll
    for (int mt = 0; mt < 4; mt++)
#pragma unroll
        for (int nt = 0; nt < 4; nt++)
#pragma unroll
            for (int r = 0; r < 4; r++) acc[mt][nt][r] = 0.f;

    issue_stage(0); issue_stage(1); issue_stage(2); issue_stage(3);

    for (int it = 0; it < NIT; it++) {
        CPA_WAIT(3);
        __syncthreads();
        issue_stage(it + 4);

        const uint32_t sb = su + (uint32_t)(it % NSTG) * STG_B;
        const uint32_t sA = sb + aw_off;
        const uint32_t sB = sb + bw_off;
#pragma unroll
        for (int k16 = 0; k16 < 2; k16++) {
            uint32_t af[4][4];
#pragma unroll
            for (int mt = 0; mt < 4; mt++)
                LDSM4(af[mt][0], af[mt][1], af[mt][2], af[mt][3],
                      sA + mt * 1280 + k16 * 32);
            uint32_t bf[2][4];
#pragma unroll
            for (int p = 0; p < 2; p++)
                LDSM4(bf[p][0], bf[p][1], bf[p][2], bf[p][3],
                      sB + p * 1280 + k16 * 32);
#pragma unroll
            for (int mt = 0; mt < 4; mt++)
#pragma unroll
                for (int nt = 0; nt < 4; nt++)
                    mma_f16(acc[mt][nt], af[mt],
                            bf[nt >> 1][(nt & 1) * 2], bf[nt >> 1][(nt & 1) * 2 + 1]);
        }

        if ((it & 31) == 31) {
            const int ct = it >> 5;
#pragma unroll
            for (int mt = 0; mt < 4; mt++)
#pragma unroll
                for (int rr = 0; rr < 2; rr++) {
                    float v = 0.f;
#pragma unroll
                    for (int nt = 0; nt < 4; nt++) {
                        int col = ct * 128 + wx * 32 + nt * 8 + gt * 2;
                        float x0 = acc[mt][nt][rr * 2 + 0] + sab2[col];
                        float x1 = acc[mt][nt][rr * 2 + 1] + sab2[col + 1];
                        v += tanh_fast(x0) * sw3[col] + tanh_fast(x1) * sw3[col + 1];
                    }
                    lsum[mt * 2 + rr] += v;
                }
#pragma unroll
            for (int mt = 0; mt < 4; mt++)
#pragma unroll
                for (int nt = 0; nt < 4; nt++)
#pragma unroll
                    for (int r = 0; r < 4; r++) acc[mt][nt][r] = 0.f;
        }
    }

    // reduce across quad lanes (cols), then across the 4 col-band warps
#pragma unroll
    for (int i = 0; i < 8; i++) {
        float v = lsum[i];
        v += __shfl_xor_sync(0xffffffffu, v, 1);
        v += __shfl_xor_sync(0xffffffffu, v, 2);
        if (gt == 0) {
            int lr = wy * 64 + (i >> 1) * 16 + (i & 1) * 8 + gq;
            sred[wx * 128 + lr] = v;
        }
    }
    __syncthreads();
    if (tid < 128) {
        float v = (sred[tid] + sred[128 + tid]) + (sred[256 + tid] + sred[384 + tid]);
        g_logits[r0 + tid] = v;
    }
}

// ---------------- kernel 5: zero ----------------
__global__ void k_zero(float* __restrict__ out) {
    int i = blockIdx.x * blockDim.x + threadIdx.x;
    if (i < OUT_FILLED) out[i] = 0.f;
}

// ---------------- kernel 6: value head ----------------
__global__ void k_value(const float* __restrict__ ef,
                        const float* __restrict__ cW1, const float* __restrict__ cb1,
                        const float* __restrict__ cW2, const float* __restrict__ cb2,
                        const float* __restrict__ cW3, const float* __restrict__ cb3,
                        float* __restrict__ out) {
    __shared__ float sg[H];
    __shared__ float h1[HC];
    __shared__ float h2[HC];
    __shared__ float sr[16];
    int b = blockIdx.x;
    int tid = threadIdx.x;  // 512
    if (tid < H) sg[tid] = ef[(size_t)b * EF_BSTRIDE + tid];
    __syncthreads();
    float acc = cb1[tid];
#pragma unroll 8
    for (int h = 0; h < H; h++) acc += sg[h] * cW1[h * HC + tid];
    h1[tid] = tanhf(acc);
    __syncthreads();
    float acc2 = cb2[tid];
#pragma unroll 8
    for (int h = 0; h < HC; h++) acc2 += h1[h] * cW2[h * HC + tid];
    h2[tid] = tanhf(acc2);
    __syncthreads();
    float p = h2[tid] * cW3[tid];
#pragma unroll
    for (int o = 16; o; o >>= 1) p += __shfl_xor_sync(0xffffffffu, p, o);
    if ((tid & 31) == 0) sr[tid >> 5] = p;
    __syncthreads();
    if (tid < 16) {
        float v = sr[tid];
#pragma unroll
        for (int o = 8; o; o >>= 1) v += __shfl_xor_sync(0x0000ffffu, v, o);
        if (tid == 0) out[OUT_FILLED + b] = v + cb3[0];
    }
}

// ---------------- kernel 7: softmax + scatter ----------------
__global__ void k_softmax(float* __restrict__ out, const float* __restrict__ ab3) {
    __shared__ float slog[KA];
    __shared__ float sred2[32];
    __shared__ float sbcast;
    int b = blockIdx.x;
    int tid = threadIdx.x;  // 1024
    float b3 = ab3[0];
    for (int k = tid; k < KA; k += 1024)
        slog[k] = g_logits[b * KA + k] + b3;
    __syncthreads();

    float m = -3.4e38f;
    for (int k = tid; k < KA; k += 1024) m = fmaxf(m, slog[k]);
#pragma unroll
    for (int o = 16; o; o >>= 1) m = fmaxf(m, __shfl_xor_sync(0xffffffffu, m, o));
    if ((tid & 31) == 0) sred2[tid >> 5] = m;
    __syncthreads();
    if (tid < 32) {
        float v = sred2[tid];
#pragma unroll
        for (int o = 16; o; o >>= 1) v = fmaxf(v, __shfl_xor_sync(0xffffffffu, v, o));
        if (tid == 0) sbcast = v;
    }
    __syncthreads();
    float gmax = sbcast;

    float s = 0.f;
    for (int k = tid; k < KA; k += 1024) s += expf(slog[k] - gmax);
#pragma unroll
    for (int o = 16; o; o >>= 1) s += __shfl_xor_sync(0xffffffffu, s, o);
    if ((tid & 31) == 0) sred2[tid >> 5] = s;
    __syncthreads();
    if (tid < 32) {
        float v = sred2[tid];
#pragma unroll
        for (int o = 16; o; o >>= 1) v += __shfl_xor_sync(0xffffffffu, v, o);
        if (tid == 0) sbcast = v;
    }
    __syncthreads();
    float inv = 1.0f / sbcast;

    for (int k = tid; k < KA; k += 1024) {
        int j = g_idx[b * KA + k];
        out[(size_t)b * NN + j] = expf(slog[k] - gmax) * inv;
    }
}

// ---------------- launch ----------------
extern "C" void kernel_launch(void* const* d_in, const int* in_sizes, int n_in,
                              void* d_out, int out_size) {
    const float* ef  = (const float*)d_in[0];
    const float* aW1 = (const float*)d_in[1];
    const float* ab1 = (const float*)d_in[2];
    const float* aW2 = (const float*)d_in[3];
    const float* ab2 = (const float*)d_in[4];
    const float* aW3 = (const float*)d_in[5];
    const float* ab3 = (const float*)d_in[6];
    const float* cW1 = (const float*)d_in[7];
    const float* cb1 = (const float*)d_in[8];
    const float* cW2 = (const float*)d_in[9];
    const float* cb2 = (const float*)d_in[10];
    const float* cW3 = (const float*)d_in[11];
    const float* cb3 = (const float*)d_in[12];
    float* out = (float*)d_out;

    cudaFuncSetAttribute(k_l23, cudaFuncAttributeMaxDynamicSharedMemorySize, L23_SMEM);

    k_prep<<<1184, 256>>>(ef, aW1, ab1, aW2);           // launch 1
    k_pgemm<<<dim3(50, 16), 256>>>(ef, aW1);            // launch 2
    k_y1<<<B * KA, 256>>>();                            // launch 3
    k_l23<<<1250, 256, L23_SMEM>>>(ab2, aW3);           // launch 4 (ncu capture)
    k_zero<<<625, 512>>>(out);
    k_value<<<B, 512>>>(ef, cW1, cb1, cW2, cb2, cW3, cb3, out);
    k_softmax<<<B, 1024>>>(out, ab3);
}

// round 8
// speedup vs baseline: 6.3376x; 1.1123x over previous
#include <cuda_runtime.h>
#include <cuda_fp16.h>
#include <math.h>
#include <stdint.h>

#define B   32
#define N   100
#define H   256
#define HA  1024
#define HC  512
#define KA  5000
#define NN  10000
#define F   356
#define EF_BSTRIDE (101 * 356)
#define OUT_FILLED 320000

// ---------------- scratch ----------------
__device__ int    g_idx[B * KA];
__device__ float  g_base1[B * HA];
__device__ float  g_P1[B * N * HA];
__device__ float  g_P2[B * N * HA];
__device__ __half g_NOh[B * N * H];             // nodes as fp16 [3200][256]
__device__ __half g_W1th[HA * 512];             // aW1[256:768] transposed: [n][k]
__device__ __half g_Y1h[(size_t)B * KA * HA];   // 327 MB fp16
__device__ __half g_W2th[HA * HA];              // aW2 transposed [n][k] fp16
__device__ float  g_logits[B * KA];

// ---------------- helpers ----------------
__device__ __forceinline__ uint32_t s2u(const void* p) {
    return (uint32_t)__cvta_generic_to_shared(p);
}
__device__ __forceinline__ float tanh_fast(float x) {
    float r;
    asm("tanh.approx.f32 %0, %1;" : "=f"(r) : "f"(x));
    return r;
}
#define CPA16(dst, src) asm volatile("cp.async.cg.shared.global [%0], [%1], 16;" :: "r"(dst), "l"(src) : "memory")
#define CPA_COMMIT()    asm volatile("cp.async.commit_group;" ::: "memory")
#define CPA_WAIT(n)     asm volatile("cp.async.wait_group %0;" :: "n"(n) : "memory")

#define LDSM4(r0, r1, r2, r3, a) \
    asm volatile("ldmatrix.sync.aligned.m8n8.x4.shared.b16 {%0,%1,%2,%3}, [%4];" \
        : "=r"(r0), "=r"(r1), "=r"(r2), "=r"(r3) : "r"(a))

__device__ __forceinline__ void mma_f16(float* c, const uint32_t* a, uint32_t b0, uint32_t b1) {
    asm volatile("mma.sync.aligned.m16n8k16.row.col.f32.f16.f16.f32 "
        "{%0,%1,%2,%3}, {%4,%5,%6,%7}, {%8,%9}, {%0,%1,%2,%3};"
        : "+f"(c[0]), "+f"(c[1]), "+f"(c[2]), "+f"(c[3])
        : "r"(a[0]), "r"(a[1]), "r"(a[2]), "r"(a[3]), "r"(b0), "r"(b1));
}

// ---------------- kernel 1: fused prep ----------------
// blocks: [0,32) extract | [32,160) base1 | [160,1184) tw2 |
//         [1184,1696) tw1 transpose | [1696,1896) nodes->half
__global__ void k_prep(const float* __restrict__ ef,
                       const float* __restrict__ aW1,
                       const float* __restrict__ ab1,
                       const float* __restrict__ aW2) {
    __shared__ float sg[H];
    __shared__ float tt[32][33];
    int blk = blockIdx.x;
    int tid = threadIdx.x;

    if (blk < 32) {
        if (tid < 32) {
            int b = blk;
            int lane = tid;
            const float* base = ef + (size_t)b * EF_BSTRIDE;
            int cnt = 0;
            for (int j0 = 0; j0 < NN; j0 += 32) {
                int j = j0 + lane;
                int i = j / N;
                int c = j - i * N;
                float v = base[(size_t)(1 + i) * F + H + c];
                bool act = (v > 0.5f);
                unsigned m = __ballot_sync(0xffffffffu, act);
                if (act) {
                    int pos = cnt + __popc(m & ((1u << lane) - 1u));
                    if (pos < KA) g_idx[b * KA + pos] = j;
                }
                cnt += __popc(m);
            }
        }
    } else if (blk < 160) {
        int idx = blk - 32;
        int b = idx >> 2;
        int o = (idx & 3) * 256 + tid;
        if (tid < H) sg[tid] = ef[(size_t)b * EF_BSTRIDE + tid];
        __syncthreads();
        float acc = ab1[o];
#pragma unroll 8
        for (int h = 0; h < H; h++) acc += sg[h] * aW1[(size_t)h * HA + o];
        g_base1[b * HA + o] = acc;
    } else if (blk < 1184) {
        int bid = blk - 160;
        int bx = (bid & 31) * 32, by = (bid >> 5) * 32;
        int x = tid & 31, y = tid >> 5;   // 32 x 8
        for (int yy = y; yy < 32; yy += 8)
            tt[yy][x] = aW2[(size_t)(by + yy) * HA + bx + x];
        __syncthreads();
        for (int yy = y; yy < 32; yy += 8)
            g_W2th[(size_t)(bx + yy) * HA + by + x] = __float2half_rn(tt[x][yy]);
    } else if (blk < 1696) {
        // g_W1th[n][k] = aW1[256+k][n], n 0..1023, k 0..511
        int bid = blk - 1184;             // 0..511 = 16 k-tiles x 32 n-tiles
        int kx = (bid & 15) * 32;
        int ny = (bid >> 4) * 32;
        int x = tid & 31, y = tid >> 5;
        for (int yy = y; yy < 32; yy += 8)
            tt[yy][x] = aW1[(size_t)(256 + kx + yy) * HA + ny + x];
        __syncthreads();
        for (int yy = y; yy < 32; yy += 8)
            g_W1th[(size_t)(ny + yy) * 512 + kx + x] = __float2half_rn(tt[x][yy]);
    } else {
        // nodes -> half: 200 blocks x 16 rows x 256 cols
        int bid = blk - 1696;
        for (int i = tid; i < 16 * H; i += 256) {
            int r = bid * 16 + (i >> 8);
            int c = i & 255;
            int b = r / N;
            int n = r - b * N;
            g_NOh[r * H + c] = __float2half_rn(ef[(size_t)b * EF_BSTRIDE + (size_t)(1 + n) * F + c]);
        }
    }
}

// ---------------- kernel 2: fp16 HMMA P1/P2 GEMM ----------------
// CTA: 64 rows x 128 cols, K=256 (4 slices of 64), both P1 and P2 share A.
// 8 warps (2x4), warp tile 32x32. All 4 slices loaded up-front (no pipeline).
// stage = A(64x144=9216) + Wa(128x144=18432) + Wb(18432) = 46080; x4 = 184320.
#define PG_STG 46080
#define PG_SMEM (4 * PG_STG)
extern __shared__ __align__(128) unsigned char smraw[];

__global__ void __launch_bounds__(256, 1) k_pgemm_h() {
    const int tid = threadIdx.x;
    const int wid = tid >> 5;
    const int lane = tid & 31;
    const int wy = wid >> 2;      // 0..1 : 32-row band
    const int wx = wid & 3;       // 0..3 : 32-col band
    const int r0 = blockIdx.x * 64;
    const int c0 = blockIdx.y * 128;
    const uint32_t su = s2u(smraw);

    const int gq = lane >> 2;
    const int gt = lane & 3;

    // load all 4 K-slices
#pragma unroll
    for (int p = 0; p < 4; p++) {
        const int k0 = p * 64;
        const uint32_t sb = su + p * PG_STG;
#pragma unroll
        for (int it = 0; it < 2; it++) {               // A: 64 rows x 8 chunks
            int idx = tid + it * 256;
            int row = idx >> 3, c = idx & 7;
            CPA16(sb + (uint32_t)(row * 144 + c * 16),
                  g_NOh + (size_t)(r0 + row) * H + k0 + c * 8);
        }
#pragma unroll
        for (int it = 0; it < 4; it++) {               // Wa: 128 rows x 8 chunks
            int idx = tid + it * 256;
            int row = idx >> 3, c = idx & 7;
            CPA16(sb + 9216 + (uint32_t)(row * 144 + c * 16),
                  g_W1th + (size_t)(c0 + row) * 512 + k0 + c * 8);
        }
#pragma unroll
        for (int it = 0; it < 4; it++) {               // Wb
            int idx = tid + it * 256;
            int row = idx >> 3, c = idx & 7;
            CPA16(sb + 27648 + (uint32_t)(row * 144 + c * 16),
                  g_W1th + (size_t)(c0 + row) * 512 + 256 + k0 + c * 8);
        }
    }
    CPA_COMMIT();
    CPA_WAIT(0);
    __syncthreads();

    const uint32_t aw_off = (uint32_t)(wy * 32 * 144)
                          + (uint32_t)((lane & 15) * 144 + ((lane & 16) >> 4) * 16);
    const uint32_t bl = (uint32_t)(((lane & 7) + ((lane & 16) >> 1)) * 144 + ((lane & 8) >> 3) * 16);
    const uint32_t bwa_off = 9216  + (uint32_t)(wx * 32 * 144) + bl;
    const uint32_t bwb_off = 27648 + (uint32_t)(wx * 32 * 144) + bl;

    float acc1[2][4][4], acc2[2][4][4];
#pragma unroll
    for (int mt = 0; mt < 2; mt++)
#pragma unroll
        for (int nt = 0; nt < 4; nt++)
#pragma unroll
            for (int r = 0; r < 4; r++) { acc1[mt][nt][r] = 0.f; acc2[mt][nt][r] = 0.f; }

#pragma unroll
    for (int p = 0; p < 4; p++) {
        const uint32_t sb = su + p * PG_STG;
#pragma unroll
        for (int k16 = 0; k16 < 4; k16++) {
            uint32_t af[2][4];
#pragma unroll
            for (int mt = 0; mt < 2; mt++)
                LDSM4(af[mt][0], af[mt][1], af[mt][2], af[mt][3],
                      sb + aw_off + mt * 16 * 144 + k16 * 32);
            uint32_t ba[2][4], bb[2][4];
#pragma unroll
            for (int q = 0; q < 2; q++) {
                LDSM4(ba[q][0], ba[q][1], ba[q][2], ba[q][3],
                      sb + bwa_off + q * 16 * 144 + k16 * 32);
                LDSM4(bb[q][0], bb[q][1], bb[q][2], bb[q][3],
                      sb + bwb_off + q * 16 * 144 + k16 * 32);
            }
#pragma unroll
            for (int mt = 0; mt < 2; mt++)
#pragma unroll
                for (int nt = 0; nt < 4; nt++) {
                    mma_f16(acc1[mt][nt], af[mt],
                            ba[nt >> 1][(nt & 1) * 2], ba[nt >> 1][(nt & 1) * 2 + 1]);
                    mma_f16(acc2[mt][nt], af[mt],
                            bb[nt >> 1][(nt & 1) * 2], bb[nt >> 1][(nt & 1) * 2 + 1]);
                }
        }
    }

    // write P1/P2 (fp32)
#pragma unroll
    for (int mt = 0; mt < 2; mt++)
#pragma unroll
        for (int nt = 0; nt < 4; nt++)
#pragma unroll
            for (int rr = 0; rr < 2; rr++) {
                int row = r0 + wy * 32 + mt * 16 + rr * 8 + gq;
                int col = c0 + wx * 32 + nt * 8 + gt * 2;
                float2 v1 = make_float2(acc1[mt][nt][rr * 2], acc1[mt][nt][rr * 2 + 1]);
                float2 v2 = make_float2(acc2[mt][nt][rr * 2], acc2[mt][nt][rr * 2 + 1]);
                *(float2*)&g_P1[(size_t)row * HA + col] = v1;
                *(float2*)&g_P2[(size_t)row * HA + col] = v2;
            }
}

// ---------------- kernel 3: Y1h = half(tanh(base1 + P1[i1] + P2[i2])) ----------------
__global__ void k_y1() {
    int row = blockIdx.x;
    int b = row / KA;
    int id = g_idx[row];
    int i1 = id / N;
    int i2 = id - i1 * N;
    const float4* p1 = (const float4*)(g_P1 + (size_t)(b * N + i1) * HA);
    const float4* p2 = (const float4*)(g_P2 + (size_t)(b * N + i2) * HA);
    const float4* bs = (const float4*)(g_base1 + (size_t)b * HA);
    int t = threadIdx.x;
    float4 a = p1[t], c = p2[t], d = bs[t];
    __half2 h0 = __floats2half2_rn(tanhf(a.x + c.x + d.x), tanhf(a.y + c.y + d.y));
    __half2 h1 = __floats2half2_rn(tanhf(a.z + c.z + d.z), tanhf(a.w + c.w + d.w));
    __half2* y = (__half2*)(g_Y1h + (size_t)row * HA);
    y[t * 2]     = h0;
    y[t * 2 + 1] = h1;
}

// ---------------- kernel 4: fp16 HMMA layer2 GEMM + fused layer3 ----------------
// CTA: 256 threads, 8 warps (2x4), tile 128x128, warp tile 64x32.
// K-slice 64 (4 x m16n8k16 per iter): NIT = 8 col-tiles x 16 slices = 128.
// 3 stages x 36864 B, wait(1). Two CTAs per SM. Row stride 144 B.
#define NSTG    3
#define STG_B   36864
#define OFFB_B  18432
#define NIT     128
#define L23_SMEM (NSTG * STG_B + 2048)    // 112640/CTA; x2 = 225280
extern __shared__ __align__(128) float smf[];

__global__ void __launch_bounds__(256, 2) k_l23(const float* __restrict__ ab2,
                                                const float* __restrict__ aW3) {
    const int tid = threadIdx.x;
    const int wid = tid >> 5;
    const int lane = tid & 31;
    const int wy = wid >> 2;     // 0..1 : 64-row band
    const int wx = wid & 3;      // 0..3 : 32-col band
    const size_t r0 = (size_t)blockIdx.x * 128;

    float* sred = smf + (NSTG * STG_B) / 4;        // [4][128]
    const uint32_t su = s2u(smf);

    const int gq = lane >> 2;
    const int gt = lane & 3;

    const uint32_t aw_off = (uint32_t)(wy * 64 * 144)
                          + (uint32_t)((lane & 15) * 144 + ((lane & 16) >> 4) * 16);
    const uint32_t bw_off = OFFB_B + (uint32_t)(wx * 32 * 144)
                          + (uint32_t)(((lane & 7) + ((lane & 16) >> 1)) * 144 + ((lane & 8) >> 3) * 16);

    const __half* Ybase = g_Y1h + r0 * HA;

    auto issue_stage = [&](int p) {
        if (p < NIT) {
            const int pct = p >> 4;                // col tile 0..7
            const int k0 = (p & 15) * 64;
            const uint32_t sb = su + (uint32_t)(p % NSTG) * STG_B;
            const __half* Ab = Ybase + k0;
            const __half* Bb = g_W2th + (size_t)(pct * 128) * HA + k0;
#pragma unroll
            for (int it = 0; it < 4; it++) {       // 128 rows x 8 chunks each
                int idx = tid + it * 256;
                int row = idx >> 3, c = idx & 7;
                CPA16(sb + (uint32_t)(row * 144 + c * 16), Ab + (size_t)row * HA + c * 8);
                CPA16(sb + OFFB_B + (uint32_t)(row * 144 + c * 16), Bb + (size_t)row * HA + c * 8);
            }
        }
        CPA_COMMIT();
    };

    float lsum[8];
#pragma unroll
    for (int i = 0; i < 8; i++) lsum[i] = 0.f;

    float acc[4][4][4];
#pragma unroll
    for (int mt = 0; mt < 4; mt++)
#pragma unroll
        for (int nt = 0; nt < 4; nt++)
#pragma unroll
            for (int r = 0; r < 4; r++) acc[mt][nt][r] = 0.f;

    issue_stage(0); issue_stage(1);

    for (int it = 0; it < NIT; it++) {
        CPA_WAIT(1);
        __syncthreads();
        issue_stage(it + 2);

        const uint32_t sb = su + (uint32_t)(it % NSTG) * STG_B;
        const uint32_t sA = sb + aw_off;
        const uint32_t sB = sb + bw_off;
#pragma unroll
        for (int k16 = 0; k16 < 4; k16++) {
            uint32_t af[4][4];
#pragma unroll
            for (int mt = 0; mt < 4; mt++)
                LDSM4(af[mt][0], af[mt][1], af[mt][2], af[mt][3],
                      sA + mt * 16 * 144 + k16 * 32);
            uint32_t bf[2][4];
#pragma unroll
            for (int p = 0; p < 2; p++)
                LDSM4(bf[p][0], bf[p][1], bf[p][2], bf[p][3],
                      sB + p * 16 * 144 + k16 * 32);
#pragma unroll
            for (int mt = 0; mt < 4; mt++)
#pragma unroll
                for (int nt = 0; nt < 4; nt++)
                    mma_f16(acc[mt][nt], af[mt],
                            bf[nt >> 1][(nt & 1) * 2], bf[nt >> 1][(nt & 1) * 2 + 1]);
        }

        if ((it & 15) == 15) {
            const int ct = it >> 4;
#pragma unroll
            for (int mt = 0; mt < 4; mt++)
#pragma unroll
                for (int rr = 0; rr < 2; rr++) {
                    float v = 0.f;
#pragma unroll
                    for (int nt = 0; nt < 4; nt++) {
                        int col = ct * 128 + wx * 32 + nt * 8 + gt * 2;
                        float b2a = __ldg(ab2 + col);
                        float b2b = __ldg(ab2 + col + 1);
                        float w3a = __ldg(aW3 + col);
                        float w3b = __ldg(aW3 + col + 1);
                        float x0 = acc[mt][nt][rr * 2 + 0] + b2a;
                        float x1 = acc[mt][nt][rr * 2 + 1] + b2b;
                        v += tanh_fast(x0) * w3a + tanh_fast(x1) * w3b;
                    }
                    lsum[mt * 2 + rr] += v;
                }
#pragma unroll
            for (int mt = 0; mt < 4; mt++)
#pragma unroll
                for (int nt = 0; nt < 4; nt++)
#pragma unroll
                    for (int r = 0; r < 4; r++) acc[mt][nt][r] = 0.f;
        }
    }

    // reduce across quad lanes (cols), then across the 4 col-band warps
#pragma unroll
    for (int i = 0; i < 8; i++) {
        float v = lsum[i];
        v += __shfl_xor_sync(0xffffffffu, v, 1);
        v += __shfl_xor_sync(0xffffffffu, v, 2);
        if (gt == 0) {
            int lr = wy * 64 + (i >> 1) * 16 + (i & 1) * 8 + gq;
            sred[wx * 128 + lr] = v;
        }
    }
    __syncthreads();
    if (tid < 128) {
        float v = (sred[tid] + sred[128 + tid]) + (sred[256 + tid] + sred[384 + tid]);
        g_logits[r0 + tid] = v;
    }
}

// ---------------- kernel 5: zero ----------------
__global__ void k_zero(float* __restrict__ out) {
    int i = blockIdx.x * blockDim.x + threadIdx.x;
    if (i < OUT_FILLED) out[i] = 0.f;
}

// ---------------- kernel 6: value head ----------------
__global__ void k_value(const float* __restrict__ ef,
                        const float* __restrict__ cW1, const float* __restrict__ cb1,
                        const float* __restrict__ cW2, const float* __restrict__ cb2,
                        const float* __restrict__ cW3, const float* __restrict__ cb3,
                        float* __restrict__ out) {
    __shared__ float sg[H];
    __shared__ float h1[HC];
    __shared__ float h2[HC];
    __shared__ float sr[16];
    int b = blockIdx.x;
    int tid = threadIdx.x;  // 512
    if (tid < H) sg[tid] = ef[(size_t)b * EF_BSTRIDE + tid];
    __syncthreads();
    float acc = cb1[tid];
#pragma unroll 8
    for (int h = 0; h < H; h++) acc += sg[h] * cW1[h * HC + tid];
    h1[tid] = tanhf(acc);
    __syncthreads();
    float acc2 = cb2[tid];
#pragma unroll 8
    for (int h = 0; h < HC; h++) acc2 += h1[h] * cW2[h * HC + tid];
    h2[tid] = tanhf(acc2);
    __syncthreads();
    float p = h2[tid] * cW3[tid];
#pragma unroll
    for (int o = 16; o; o >>= 1) p += __shfl_xor_sync(0xffffffffu, p, o);
    if ((tid & 31) == 0) sr[tid >> 5] = p;
    __syncthreads();
    if (tid < 16) {
        float v = sr[tid];
#pragma unroll
        for (int o = 8; o; o >>= 1) v += __shfl_xor_sync(0x0000ffffu, v, o);
        if (tid == 0) out[OUT_FILLED + b] = v + cb3[0];
    }
}

// ---------------- kernel 7: softmax + scatter ----------------
__global__ void k_softmax(float* __restrict__ out, const float* __restrict__ ab3) {
    __shared__ float slog[KA];
    __shared__ float sred2[32];
    __shared__ float sbcast;
    int b = blockIdx.x;
    int tid = threadIdx.x;  // 1024
    float b3 = ab3[0];
    for (int k = tid; k < KA; k += 1024)
        slog[k] = g_logits[b * KA + k] + b3;
    __syncthreads();

    float m = -3.4e38f;
    for (int k = tid; k < KA; k += 1024) m = fmaxf(m, slog[k]);
#pragma unroll
    for (int o = 16; o; o >>= 1) m = fmaxf(m, __shfl_xor_sync(0xffffffffu, m, o));
    if ((tid & 31) == 0) sred2[tid >> 5] = m;
    __syncthreads();
    if (tid < 32) {
        float v = sred2[tid];
#pragma unroll
        for (int o = 16; o; o >>= 1) v = fmaxf(v, __shfl_xor_sync(0xffffffffu, v, o));
        if (tid == 0) sbcast = v;
    }
    __syncthreads();
    float gmax = sbcast;

    float s = 0.f;
    for (int k = tid; k < KA; k += 1024) s += expf(slog[k] - gmax);
#pragma unroll
    for (int o = 16; o; o >>= 1) s += __shfl_xor_sync(0xffffffffu, s, o);
    if ((tid & 31) == 0) sred2[tid >> 5] = s;
    __syncthreads();
    if (tid < 32) {
        float v = sred2[tid];
#pragma unroll
        for (int o = 16; o; o >>= 1) v += __shfl_xor_sync(0xffffffffu, v, o);
        if (tid == 0) sbcast = v;
    }
    __syncthreads();
    float inv = 1.0f / sbcast;

    for (int k = tid; k < KA; k += 1024) {
        int j = g_idx[b * KA + k];
        out[(size_t)b * NN + j] = expf(slog[k] - gmax) * inv;
    }
}

// ---------------- launch ----------------
extern "C" void kernel_launch(void* const* d_in, const int* in_sizes, int n_in,
                              void* d_out, int out_size) {
    const float* ef  = (const float*)d_in[0];
    const float* aW1 = (const float*)d_in[1];
    const float* ab1 = (const float*)d_in[2];
    const float* aW2 = (const float*)d_in[3];
    const float* ab2 = (const float*)d_in[4];
    const float* aW3 = (const float*)d_in[5];
    const float* ab3 = (const float*)d_in[6];
    const float* cW1 = (const float*)d_in[7];
    const float* cb1 = (const float*)d_in[8];
    const float* cW2 = (const float*)d_in[9];
    const float* cb2 = (const float*)d_in[10];
    const float* cW3 = (const float*)d_in[11];
    const float* cb3 = (const float*)d_in[12];
    float* out = (float*)d_out;

    cudaFuncSetAttribute(k_l23, cudaFuncAttributeMaxDynamicSharedMemorySize, L23_SMEM);
    cudaFuncSetAttribute(k_pgemm_h, cudaFuncAttributeMaxDynamicSharedMemorySize, PG_SMEM);

    k_prep<<<1896, 256>>>(ef, aW1, ab1, aW2);           // launch 1
    k_pgemm_h<<<dim3(50, 8), 256, PG_SMEM>>>();         // launch 2
    k_y1<<<B * KA, 256>>>();                            // launch 3
    k_l23<<<1250, 256, L23_SMEM>>>(ab2, aW3);           // launch 4 (ncu capture)
    k_zero<<<625, 512>>>(out);
    k_value<<<B, 512>>>(ef, cW1, cb1, cW2, cb2, cW3, cb3, out);
    k_softmax<<<B, 1024>>>(out, ab3);
}

// round 9
// speedup vs baseline: 6.9437x; 1.0956x over previous
#include <cuda_runtime.h>
#include <cuda_fp16.h>
#include <math.h>
#include <stdint.h>

#define B   32
#define N   100
#define H   256
#define HA  1024
#define HC  512
#define KA  5000
#define NN  10000
#define F   356
#define EF_BSTRIDE (101 * 356)
#define OUT_FILLED 320000

// ---------------- scratch ----------------
__device__ int    g_idx[B * KA];
__device__ float  g_base1[B * HA];
__device__ float  g_P1[B * N * HA];
__device__ float  g_P2[B * N * HA];
__device__ __half g_NOh[B * N * H];             // nodes as fp16 [3200][256]
__device__ __half g_W1th[HA * 512];             // aW1[256:768] transposed: [n][k]
__device__ __half g_Y1h[(size_t)B * KA * HA];   // 327 MB fp16
__device__ __half g_W2th[HA * HA];              // aW2 transposed [n][k] fp16
__device__ float  g_logits[B * KA];

// ---------------- helpers ----------------
__device__ __forceinline__ uint32_t s2u(const void* p) {
    return (uint32_t)__cvta_generic_to_shared(p);
}
__device__ __forceinline__ float tanh_fast(float x) {
    float r;
    asm("tanh.approx.f32 %0, %1;" : "=f"(r) : "f"(x));
    return r;
}
#define CPA16(dst, src) asm volatile("cp.async.cg.shared.global [%0], [%1], 16;" :: "r"(dst), "l"(src) : "memory")
#define CPA_COMMIT()    asm volatile("cp.async.commit_group;" ::: "memory")
#define CPA_WAIT(n)     asm volatile("cp.async.wait_group %0;" :: "n"(n) : "memory")

#define LDSM4(r0, r1, r2, r3, a) \
    asm volatile("ldmatrix.sync.aligned.m8n8.x4.shared.b16 {%0,%1,%2,%3}, [%4];" \
        : "=r"(r0), "=r"(r1), "=r"(r2), "=r"(r3) : "r"(a))

__device__ __forceinline__ void mma_f16(float* c, const uint32_t* a, uint32_t b0, uint32_t b1) {
    asm volatile("mma.sync.aligned.m16n8k16.row.col.f32.f16.f16.f32 "
        "{%0,%1,%2,%3}, {%4,%5,%6,%7}, {%8,%9}, {%0,%1,%2,%3};"
        : "+f"(c[0]), "+f"(c[1]), "+f"(c[2]), "+f"(c[3])
        : "r"(a[0]), "r"(a[1]), "r"(a[2]), "r"(a[3]), "r"(b0), "r"(b1));
}

// ---------------- kernel 1: fused prep ----------------
// blocks: [0,32) extract | [32,160) base1 | [160,1184) tw2 |
//         [1184,1696) tw1 transpose | [1696,1896) nodes->half
__global__ void k_prep(const float* __restrict__ ef,
                       const float* __restrict__ aW1,
                       const float* __restrict__ ab1,
                       const float* __restrict__ aW2) {
    __shared__ float sg[H];
    __shared__ float tt[32][33];
    int blk = blockIdx.x;
    int tid = threadIdx.x;

    if (blk < 32) {
        if (tid < 32) {
            int b = blk;
            int lane = tid;
            const float* base = ef + (size_t)b * EF_BSTRIDE;
            int cnt = 0;
            for (int j0 = 0; j0 < NN; j0 += 32) {
                int j = j0 + lane;
                int i = j / N;
                int c = j - i * N;
                float v = base[(size_t)(1 + i) * F + H + c];
                bool act = (v > 0.5f);
                unsigned m = __ballot_sync(0xffffffffu, act);
                if (act) {
                    int pos = cnt + __popc(m & ((1u << lane) - 1u));
                    if (pos < KA) g_idx[b * KA + pos] = j;
                }
                cnt += __popc(m);
            }
        }
    } else if (blk < 160) {
        int idx = blk - 32;
        int b = idx >> 2;
        int o = (idx & 3) * 256 + tid;
        if (tid < H) sg[tid] = ef[(size_t)b * EF_BSTRIDE + tid];
        __syncthreads();
        float acc = ab1[o];
#pragma unroll 8
        for (int h = 0; h < H; h++) acc += sg[h] * aW1[(size_t)h * HA + o];
        g_base1[b * HA + o] = acc;
    } else if (blk < 1184) {
        int bid = blk - 160;
        int bx = (bid & 31) * 32, by = (bid >> 5) * 32;
        int x = tid & 31, y = tid >> 5;   // 32 x 8
        for (int yy = y; yy < 32; yy += 8)
            tt[yy][x] = aW2[(size_t)(by + yy) * HA + bx + x];
        __syncthreads();
        for (int yy = y; yy < 32; yy += 8)
            g_W2th[(size_t)(bx + yy) * HA + by + x] = __float2half_rn(tt[x][yy]);
    } else if (blk < 1696) {
        // g_W1th[n][k] = aW1[256+k][n], n 0..1023, k 0..511
        int bid = blk - 1184;             // 0..511 = 16 k-tiles x 32 n-tiles
        int kx = (bid & 15) * 32;
        int ny = (bid >> 4) * 32;
        int x = tid & 31, y = tid >> 5;
        for (int yy = y; yy < 32; yy += 8)
            tt[yy][x] = aW1[(size_t)(256 + kx + yy) * HA + ny + x];
        __syncthreads();
        for (int yy = y; yy < 32; yy += 8)
            g_W1th[(size_t)(ny + yy) * 512 + kx + x] = __float2half_rn(tt[x][yy]);
    } else {
        // nodes -> half: 200 blocks x 16 rows x 256 cols
        int bid = blk - 1696;
        for (int i = tid; i < 16 * H; i += 256) {
            int r = bid * 16 + (i >> 8);
            int c = i & 255;
            int b = r / N;
            int n = r - b * N;
            g_NOh[r * H + c] = __float2half_rn(ef[(size_t)b * EF_BSTRIDE + (size_t)(1 + n) * F + c]);
        }
    }
}

// ---------------- kernel 2: fp16 HMMA P1/P2 GEMM ----------------
#define PG_STG 46080
#define PG_SMEM (4 * PG_STG)
extern __shared__ __align__(128) unsigned char smraw[];

__global__ void __launch_bounds__(256, 1) k_pgemm_h() {
    const int tid = threadIdx.x;
    const int wid = tid >> 5;
    const int lane = tid & 31;
    const int wy = wid >> 2;      // 0..1 : 32-row band
    const int wx = wid & 3;       // 0..3 : 32-col band
    const int r0 = blockIdx.x * 64;
    const int c0 = blockIdx.y * 128;
    const uint32_t su = s2u(smraw);

    const int gq = lane >> 2;
    const int gt = lane & 3;

#pragma unroll
    for (int p = 0; p < 4; p++) {
        const int k0 = p * 64;
        const uint32_t sb = su + p * PG_STG;
#pragma unroll
        for (int it = 0; it < 2; it++) {               // A: 64 rows x 8 chunks
            int idx = tid + it * 256;
            int row = idx >> 3, c = idx & 7;
            CPA16(sb + (uint32_t)(row * 144 + c * 16),
                  g_NOh + (size_t)(r0 + row) * H + k0 + c * 8);
        }
#pragma unroll
        for (int it = 0; it < 4; it++) {               // Wa: 128 rows x 8 chunks
            int idx = tid + it * 256;
            int row = idx >> 3, c = idx & 7;
            CPA16(sb + 9216 + (uint32_t)(row * 144 + c * 16),
                  g_W1th + (size_t)(c0 + row) * 512 + k0 + c * 8);
        }
#pragma unroll
        for (int it = 0; it < 4; it++) {               // Wb
            int idx = tid + it * 256;
            int row = idx >> 3, c = idx & 7;
            CPA16(sb + 27648 + (uint32_t)(row * 144 + c * 16),
                  g_W1th + (size_t)(c0 + row) * 512 + 256 + k0 + c * 8);
        }
    }
    CPA_COMMIT();
    CPA_WAIT(0);
    __syncthreads();

    const uint32_t aw_off = (uint32_t)(wy * 32 * 144)
                          + (uint32_t)((lane & 15) * 144 + ((lane & 16) >> 4) * 16);
    const uint32_t bl = (uint32_t)(((lane & 7) + ((lane & 16) >> 1)) * 144 + ((lane & 8) >> 3) * 16);
    const uint32_t bwa_off = 9216  + (uint32_t)(wx * 32 * 144) + bl;
    const uint32_t bwb_off = 27648 + (uint32_t)(wx * 32 * 144) + bl;

    float acc1[2][4][4], acc2[2][4][4];
#pragma unroll
    for (int mt = 0; mt < 2; mt++)
#pragma unroll
        for (int nt = 0; nt < 4; nt++)
#pragma unroll
            for (int r = 0; r < 4; r++) { acc1[mt][nt][r] = 0.f; acc2[mt][nt][r] = 0.f; }

#pragma unroll
    for (int p = 0; p < 4; p++) {
        const uint32_t sb = su + p * PG_STG;
#pragma unroll
        for (int k16 = 0; k16 < 4; k16++) {
            uint32_t af[2][4];
#pragma unroll
            for (int mt = 0; mt < 2; mt++)
                LDSM4(af[mt][0], af[mt][1], af[mt][2], af[mt][3],
                      sb + aw_off + mt * 16 * 144 + k16 * 32);
            uint32_t ba[2][4], bb[2][4];
#pragma unroll
            for (int q = 0; q < 2; q++) {
                LDSM4(ba[q][0], ba[q][1], ba[q][2], ba[q][3],
                      sb + bwa_off + q * 16 * 144 + k16 * 32);
                LDSM4(bb[q][0], bb[q][1], bb[q][2], bb[q][3],
                      sb + bwb_off + q * 16 * 144 + k16 * 32);
            }
#pragma unroll
            for (int mt = 0; mt < 2; mt++)
#pragma unroll
                for (int nt = 0; nt < 4; nt++) {
                    mma_f16(acc1[mt][nt], af[mt],
                            ba[nt >> 1][(nt & 1) * 2], ba[nt >> 1][(nt & 1) * 2 + 1]);
                    mma_f16(acc2[mt][nt], af[mt],
                            bb[nt >> 1][(nt & 1) * 2], bb[nt >> 1][(nt & 1) * 2 + 1]);
                }
        }
    }

#pragma unroll
    for (int mt = 0; mt < 2; mt++)
#pragma unroll
        for (int nt = 0; nt < 4; nt++)
#pragma unroll
            for (int rr = 0; rr < 2; rr++) {
                int row = r0 + wy * 32 + mt * 16 + rr * 8 + gq;
                int col = c0 + wx * 32 + nt * 8 + gt * 2;
                float2 v1 = make_float2(acc1[mt][nt][rr * 2], acc1[mt][nt][rr * 2 + 1]);
                float2 v2 = make_float2(acc2[mt][nt][rr * 2], acc2[mt][nt][rr * 2 + 1]);
                *(float2*)&g_P1[(size_t)row * HA + col] = v1;
                *(float2*)&g_P2[(size_t)row * HA + col] = v2;
            }
}

// ---------------- kernel 3: Y1h = half(tanh.approx(base1 + P1[i1] + P2[i2])) ----------------
// tanh.approx error (2^-11) is the same magnitude as the fp16 rounding applied
// immediately after, so it is precision-free here.
__global__ void k_y1() {
    int row = blockIdx.x;
    int b = row / KA;
    int id = g_idx[row];
    int i1 = id / N;
    int i2 = id - i1 * N;
    const float4* p1 = (const float4*)(g_P1 + (size_t)(b * N + i1) * HA);
    const float4* p2 = (const float4*)(g_P2 + (size_t)(b * N + i2) * HA);
    const float4* bs = (const float4*)(g_base1 + (size_t)b * HA);
    int t = threadIdx.x;
    float4 a = p1[t], c = p2[t], d = bs[t];
    __half2 h0 = __floats2half2_rn(tanh_fast(a.x + c.x + d.x), tanh_fast(a.y + c.y + d.y));
    __half2 h1 = __floats2half2_rn(tanh_fast(a.z + c.z + d.z), tanh_fast(a.w + c.w + d.w));
    __half2* y = (__half2*)(g_Y1h + (size_t)row * HA);
    y[t * 2]     = h0;
    y[t * 2 + 1] = h1;
}

// ---------------- kernel 4: fp16 HMMA layer2 GEMM + fused layer3 ----------------
// CTA: 256 threads, 8 warps (2x4), tile 128x128, warp tile 64x32.
// K-slice 64 (4 x m16n8k16 per iter): NIT = 8 col-tiles x 16 slices = 128.
// 3 stages x 36864 B, wait(1). Two CTAs per SM. Row stride 144 B.
// Producer issue is placed AFTER the first k16 group to spread LSU pressure.
#define NSTG    3
#define STG_B   36864
#define OFFB_B  18432
#define NIT     128
#define L23_SMEM (NSTG * STG_B + 2048)    // 112640/CTA; x2 = 225280
extern __shared__ __align__(128) float smf[];

__global__ void __launch_bounds__(256, 2) k_l23(const float* __restrict__ ab2,
                                                const float* __restrict__ aW3) {
    const int tid = threadIdx.x;
    const int wid = tid >> 5;
    const int lane = tid & 31;
    const int wy = wid >> 2;     // 0..1 : 64-row band
    const int wx = wid & 3;      // 0..3 : 32-col band
    const size_t r0 = (size_t)blockIdx.x * 128;

    float* sred = smf + (NSTG * STG_B) / 4;        // [4][128]
    const uint32_t su = s2u(smf);

    const int gq = lane >> 2;
    const int gt = lane & 3;

    const uint32_t aw_off = (uint32_t)(wy * 64 * 144)
                          + (uint32_t)((lane & 15) * 144 + ((lane & 16) >> 4) * 16);
    const uint32_t bw_off = OFFB_B + (uint32_t)(wx * 32 * 144)
                          + (uint32_t)(((lane & 7) + ((lane & 16) >> 1)) * 144 + ((lane & 8) >> 3) * 16);

    const __half* Ybase = g_Y1h + r0 * HA;

    auto issue_stage = [&](int p) {
        if (p < NIT) {
            const int pct = p >> 4;                // col tile 0..7
            const int k0 = (p & 15) * 64;
            const uint32_t sb = su + (uint32_t)(p % NSTG) * STG_B;
            const __half* Ab = Ybase + k0;
            const __half* Bb = g_W2th + (size_t)(pct * 128) * HA + k0;
#pragma unroll
            for (int it = 0; it < 4; it++) {       // 128 rows x 8 chunks each
                int idx = tid + it * 256;
                int row = idx >> 3, c = idx & 7;
                CPA16(sb + (uint32_t)(row * 144 + c * 16), Ab + (size_t)row * HA + c * 8);
                CPA16(sb + OFFB_B + (uint32_t)(row * 144 + c * 16), Bb + (size_t)row * HA + c * 8);
            }
        }
        CPA_COMMIT();
    };

    float lsum[8];
#pragma unroll
    for (int i = 0; i < 8; i++) lsum[i] = 0.f;

    float acc[4][4][4];
#pragma unroll
    for (int mt = 0; mt < 4; mt++)
#pragma unroll
        for (int nt = 0; nt < 4; nt++)
#pragma unroll
            for (int r = 0; r < 4; r++) acc[mt][nt][r] = 0.f;

    issue_stage(0); issue_stage(1);

    for (int it = 0; it < NIT; it++) {
        CPA_WAIT(1);
        __syncthreads();

        const uint32_t sb = su + (uint32_t)(it % NSTG) * STG_B;
        const uint32_t sA = sb + aw_off;
        const uint32_t sB = sb + bw_off;

        // ---- k16 = 0 first, then producer issue, then k16 = 1..3 ----
#pragma unroll
        for (int k16 = 0; k16 < 4; k16++) {
            uint32_t af[4][4];
#pragma unroll
            for (int mt = 0; mt < 4; mt++)
                LDSM4(af[mt][0], af[mt][1], af[mt][2], af[mt][3],
                      sA + mt * 16 * 144 + k16 * 32);
            uint32_t bf[2][4];
#pragma unroll
            for (int p = 0; p < 2; p++)
                LDSM4(bf[p][0], bf[p][1], bf[p][2], bf[p][3],
                      sB + p * 16 * 144 + k16 * 32);
#pragma unroll
            for (int mt = 0; mt < 4; mt++)
#pragma unroll
                for (int nt = 0; nt < 4; nt++)
                    mma_f16(acc[mt][nt], af[mt],
                            bf[nt >> 1][(nt & 1) * 2], bf[nt >> 1][(nt & 1) * 2 + 1]);
            if (k16 == 0) issue_stage(it + 2);
        }

        if ((it & 15) == 15) {
            const int ct = it >> 4;
#pragma unroll
            for (int mt = 0; mt < 4; mt++)
#pragma unroll
                for (int rr = 0; rr < 2; rr++) {
                    float v = 0.f;
#pragma unroll
                    for (int nt = 0; nt < 4; nt++) {
                        int col = ct * 128 + wx * 32 + nt * 8 + gt * 2;
                        float b2a = __ldg(ab2 + col);
                        float b2b = __ldg(ab2 + col + 1);
                        float w3a = __ldg(aW3 + col);
                        float w3b = __ldg(aW3 + col + 1);
                        float x0 = acc[mt][nt][rr * 2 + 0] + b2a;
                        float x1 = acc[mt][nt][rr * 2 + 1] + b2b;
                        v += tanh_fast(x0) * w3a + tanh_fast(x1) * w3b;
                    }
                    lsum[mt * 2 + rr] += v;
                }
#pragma unroll
            for (int mt = 0; mt < 4; mt++)
#pragma unroll
                for (int nt = 0; nt < 4; nt++)
#pragma unroll
                    for (int r = 0; r < 4; r++) acc[mt][nt][r] = 0.f;
        }
    }

#pragma unroll
    for (int i = 0; i < 8; i++) {
        float v = lsum[i];
        v += __shfl_xor_sync(0xffffffffu, v, 1);
        v += __shfl_xor_sync(0xffffffffu, v, 2);
        if (gt == 0) {
            int lr = wy * 64 + (i >> 1) * 16 + (i & 1) * 8 + gq;
            sred[wx * 128 + lr] = v;
        }
    }
    __syncthreads();
    if (tid < 128) {
        float v = (sred[tid] + sred[128 + tid]) + (sred[256 + tid] + sred[384 + tid]);
        g_logits[r0 + tid] = v;
    }
}

// ---------------- kernel 5: value head ----------------
__global__ void k_value(const float* __restrict__ ef,
                        const float* __restrict__ cW1, const float* __restrict__ cb1,
                        const float* __restrict__ cW2, const float* __restrict__ cb2,
                        const float* __restrict__ cW3, const float* __restrict__ cb3,
                        float* __restrict__ out) {
    __shared__ float sg[H];
    __shared__ float h1[HC];
    __shared__ float h2[HC];
    __shared__ float sr[16];
    int b = blockIdx.x;
    int tid = threadIdx.x;  // 512
    if (tid < H) sg[tid] = ef[(size_t)b * EF_BSTRIDE + tid];
    __syncthreads();
    float acc = cb1[tid];
#pragma unroll 8
    for (int h = 0; h < H; h++) acc += sg[h] * cW1[h * HC + tid];
    h1[tid] = tanhf(acc);
    __syncthreads();
    float acc2 = cb2[tid];
#pragma unroll 8
    for (int h = 0; h < HC; h++) acc2 += h1[h] * cW2[h * HC + tid];
    h2[tid] = tanhf(acc2);
    __syncthreads();
    float p = h2[tid] * cW3[tid];
#pragma unroll
    for (int o = 16; o; o >>= 1) p += __shfl_xor_sync(0xffffffffu, p, o);
    if ((tid & 31) == 0) sr[tid >> 5] = p;
    __syncthreads();
    if (tid < 16) {
        float v = sr[tid];
#pragma unroll
        for (int o = 8; o; o >>= 1) v += __shfl_xor_sync(0x0000ffffu, v, o);
        if (tid == 0) out[OUT_FILLED + b] = v + cb3[0];
    }
}

// ---------------- kernel 6: softmax + zero + scatter (fused) ----------------
__global__ void k_softmax(float* __restrict__ out, const float* __restrict__ ab3) {
    __shared__ float slog[KA];
    __shared__ float sred2[32];
    __shared__ float sbcast;
    int b = blockIdx.x;
    int tid = threadIdx.x;  // 1024
    float b3 = ab3[0];

    // zero this batch's filled row (replaces k_zero)
    for (int k = tid; k < NN; k += 1024)
        out[(size_t)b * NN + k] = 0.f;

    for (int k = tid; k < KA; k += 1024)
        slog[k] = g_logits[b * KA + k] + b3;
    __syncthreads();

    float m = -3.4e38f;
    for (int k = tid; k < KA; k += 1024) m = fmaxf(m, slog[k]);
#pragma unroll
    for (int o = 16; o; o >>= 1) m = fmaxf(m, __shfl_xor_sync(0xffffffffu, m, o));
    if ((tid & 31) == 0) sred2[tid >> 5] = m;
    __syncthreads();
    if (tid < 32) {
        float v = sred2[tid];
#pragma unroll
        for (int o = 16; o; o >>= 1) v = fmaxf(v, __shfl_xor_sync(0xffffffffu, v, o));
        if (tid == 0) sbcast = v;
    }
    __syncthreads();
    float gmax = sbcast;

    float s = 0.f;
    for (int k = tid; k < KA; k += 1024) s += expf(slog[k] - gmax);
#pragma unroll
    for (int o = 16; o; o >>= 1) s += __shfl_xor_sync(0xffffffffu, s, o);
    if ((tid & 31) == 0) sred2[tid >> 5] = s;
    __syncthreads();
    if (tid < 32) {
        float v = sred2[tid];
#pragma unroll
        for (int o = 16; o; o >>= 1) v += __shfl_xor_sync(0xffffffffu, v, o);
        if (tid == 0) sbcast = v;
    }
    __syncthreads();
    float inv = 1.0f / sbcast;

    for (int k = tid; k < KA; k += 1024) {
        int j = g_idx[b * KA + k];
        out[(size_t)b * NN + j] = expf(slog[k] - gmax) * inv;
    }
}

// ---------------- launch ----------------
extern "C" void kernel_launch(void* const* d_in, const int* in_sizes, int n_in,
                              void* d_out, int out_size) {
    const float* ef  = (const float*)d_in[0];
    const float* aW1 = (const float*)d_in[1];
    const float* ab1 = (const float*)d_in[2];
    const float* aW2 = (const float*)d_in[3];
    const float* ab2 = (const float*)d_in[4];
    const float* aW3 = (const float*)d_in[5];
    const float* ab3 = (const float*)d_in[6];
    const float* cW1 = (const float*)d_in[7];
    const float* cb1 = (const float*)d_in[8];
    const float* cW2 = (const float*)d_in[9];
    const float* cb2 = (const float*)d_in[10];
    const float* cW3 = (const float*)d_in[11];
    const float* cb3 = (const float*)d_in[12];
    float* out = (float*)d_out;

    cudaFuncSetAttribute(k_l23, cudaFuncAttributeMaxDynamicSharedMemorySize, L23_SMEM);
    cudaFuncSetAttribute(k_pgemm_h, cudaFuncAttributeMaxDynamicSharedMemorySize, PG_SMEM);

    k_prep<<<1896, 256>>>(ef, aW1, ab1, aW2);           // launch 1
    k_pgemm_h<<<dim3(50, 8), 256, PG_SMEM>>>();         // launch 2
    k_y1<<<B * KA, 256>>>();                            // launch 3
    k_l23<<<1250, 256, L23_SMEM>>>(ab2, aW3);           // launch 4 (ncu capture)
    k_value<<<B, 512>>>(ef, cW1, cb1, cW2, cb2, cW3, cb3, out);
    k_softmax<<<B, 1024>>>(out, ab3);
}

// round 10
// speedup vs baseline: 7.3734x; 1.0619x over previous
#include <cuda_runtime.h>
#include <cuda_fp16.h>
#include <math.h>
#include <stdint.h>

#define B   32
#define N   100
#define H   256
#define HA  1024
#define HC  512
#define KA  5000
#define NN  10000
#define F   356
#define EF_BSTRIDE (101 * 356)
#define OUT_FILLED 320000

// ---------------- scratch ----------------
__device__ int    g_idx[B * KA];
__device__ float  g_base1[B * HA];
__device__ __half g_P1h[B * N * HA];            // fp16 partial tables (6.5 MB each)
__device__ __half g_P2h[B * N * HA];
__device__ __half g_NOh[B * N * H];             // nodes as fp16 [3200][256]
__device__ __half g_W1th[HA * 512];             // aW1[256:768] transposed: [n][k]
__device__ __half g_Y1h[(size_t)B * KA * HA];   // 327 MB fp16
__device__ __half g_W2th[HA * HA];              // aW2 transposed [n][k] fp16
__device__ float  g_logits[B * KA];

// ---------------- helpers ----------------
__device__ __forceinline__ uint32_t s2u(const void* p) {
    return (uint32_t)__cvta_generic_to_shared(p);
}
__device__ __forceinline__ float tanh_fast(float x) {
    float r;
    asm("tanh.approx.f32 %0, %1;" : "=f"(r) : "f"(x));
    return r;
}
#define CPA16(dst, src) asm volatile("cp.async.cg.shared.global [%0], [%1], 16;" :: "r"(dst), "l"(src) : "memory")
#define CPA_COMMIT()    asm volatile("cp.async.commit_group;" ::: "memory")
#define CPA_WAIT(n)     asm volatile("cp.async.wait_group %0;" :: "n"(n) : "memory")

#define LDSM4(r0, r1, r2, r3, a) \
    asm volatile("ldmatrix.sync.aligned.m8n8.x4.shared.b16 {%0,%1,%2,%3}, [%4];" \
        : "=r"(r0), "=r"(r1), "=r"(r2), "=r"(r3) : "r"(a))

__device__ __forceinline__ void mma_f16(float* c, const uint32_t* a, uint32_t b0, uint32_t b1) {
    asm volatile("mma.sync.aligned.m16n8k16.row.col.f32.f16.f16.f32 "
        "{%0,%1,%2,%3}, {%4,%5,%6,%7}, {%8,%9}, {%0,%1,%2,%3};"
        : "+f"(c[0]), "+f"(c[1]), "+f"(c[2]), "+f"(c[3])
        : "r"(a[0]), "r"(a[1]), "r"(a[2]), "r"(a[3]), "r"(b0), "r"(b1));
}

// ---------------- kernel 1: fused prep ----------------
// blocks: [0,32) extract | [32,160) base1 | [160,1184) tw2 |
//         [1184,1696) tw1 transpose | [1696,1896) nodes->half
__global__ void k_prep(const float* __restrict__ ef,
                       const float* __restrict__ aW1,
                       const float* __restrict__ ab1,
                       const float* __restrict__ aW2) {
    __shared__ float sg[H];
    __shared__ float tt[32][33];
    int blk = blockIdx.x;
    int tid = threadIdx.x;

    if (blk < 32) {
        if (tid < 32) {
            int b = blk;
            int lane = tid;
            const float* base = ef + (size_t)b * EF_BSTRIDE;
            int cnt = 0;
            for (int j0 = 0; j0 < NN; j0 += 32) {
                int j = j0 + lane;
                int i = j / N;
                int c = j - i * N;
                float v = base[(size_t)(1 + i) * F + H + c];
                bool act = (v > 0.5f);
                unsigned m = __ballot_sync(0xffffffffu, act);
                if (act) {
                    int pos = cnt + __popc(m & ((1u << lane) - 1u));
                    if (pos < KA) g_idx[b * KA + pos] = j;
                }
                cnt += __popc(m);
            }
        }
    } else if (blk < 160) {
        int idx = blk - 32;
        int b = idx >> 2;
        int o = (idx & 3) * 256 + tid;
        if (tid < H) sg[tid] = ef[(size_t)b * EF_BSTRIDE + tid];
        __syncthreads();
        float acc = ab1[o];
#pragma unroll 8
        for (int h = 0; h < H; h++) acc += sg[h] * aW1[(size_t)h * HA + o];
        g_base1[b * HA + o] = acc;
    } else if (blk < 1184) {
        int bid = blk - 160;
        int bx = (bid & 31) * 32, by = (bid >> 5) * 32;
        int x = tid & 31, y = tid >> 5;   // 32 x 8
        for (int yy = y; yy < 32; yy += 8)
            tt[yy][x] = aW2[(size_t)(by + yy) * HA + bx + x];
        __syncthreads();
        for (int yy = y; yy < 32; yy += 8)
            g_W2th[(size_t)(bx + yy) * HA + by + x] = __float2half_rn(tt[x][yy]);
    } else if (blk < 1696) {
        // g_W1th[n][k] = aW1[256+k][n], n 0..1023, k 0..511
        int bid = blk - 1184;             // 0..511 = 16 k-tiles x 32 n-tiles
        int kx = (bid & 15) * 32;
        int ny = (bid >> 4) * 32;
        int x = tid & 31, y = tid >> 5;
        for (int yy = y; yy < 32; yy += 8)
            tt[yy][x] = aW1[(size_t)(256 + kx + yy) * HA + ny + x];
        __syncthreads();
        for (int yy = y; yy < 32; yy += 8)
            g_W1th[(size_t)(ny + yy) * 512 + kx + x] = __float2half_rn(tt[x][yy]);
    } else {
        // nodes -> half: 200 blocks x 16 rows x 256 cols
        int bid = blk - 1696;
        for (int i = tid; i < 16 * H; i += 256) {
            int r = bid * 16 + (i >> 8);
            int c = i & 255;
            int b = r / N;
            int n = r - b * N;
            g_NOh[r * H + c] = __float2half_rn(ef[(size_t)b * EF_BSTRIDE + (size_t)(1 + n) * F + c]);
        }
    }
}

// ---------------- kernel 2: fp16 HMMA P1/P2 GEMM (half output) ----------------
#define PG_STG 46080
#define PG_SMEM (4 * PG_STG)
extern __shared__ __align__(128) unsigned char smraw[];

__global__ void __launch_bounds__(256, 1) k_pgemm_h() {
    const int tid = threadIdx.x;
    const int wid = tid >> 5;
    const int lane = tid & 31;
    const int wy = wid >> 2;      // 0..1 : 32-row band
    const int wx = wid & 3;       // 0..3 : 32-col band
    const int r0 = blockIdx.x * 64;
    const int c0 = blockIdx.y * 128;
    const uint32_t su = s2u(smraw);

    const int gq = lane >> 2;
    const int gt = lane & 3;

#pragma unroll
    for (int p = 0; p < 4; p++) {
        const int k0 = p * 64;
        const uint32_t sb = su + p * PG_STG;
#pragma unroll
        for (int it = 0; it < 2; it++) {               // A: 64 rows x 8 chunks
            int idx = tid + it * 256;
            int row = idx >> 3, c = idx & 7;
            CPA16(sb + (uint32_t)(row * 144 + c * 16),
                  g_NOh + (size_t)(r0 + row) * H + k0 + c * 8);
        }
#pragma unroll
        for (int it = 0; it < 4; it++) {               // Wa: 128 rows x 8 chunks
            int idx = tid + it * 256;
            int row = idx >> 3, c = idx & 7;
            CPA16(sb + 9216 + (uint32_t)(row * 144 + c * 16),
                  g_W1th + (size_t)(c0 + row) * 512 + k0 + c * 8);
        }
#pragma unroll
        for (int it = 0; it < 4; it++) {               // Wb
            int idx = tid + it * 256;
            int row = idx >> 3, c = idx & 7;
            CPA16(sb + 27648 + (uint32_t)(row * 144 + c * 16),
                  g_W1th + (size_t)(c0 + row) * 512 + 256 + k0 + c * 8);
        }
    }
    CPA_COMMIT();
    CPA_WAIT(0);
    __syncthreads();

    const uint32_t aw_off = (uint32_t)(wy * 32 * 144)
                          + (uint32_t)((lane & 15) * 144 + ((lane & 16) >> 4) * 16);
    const uint32_t bl = (uint32_t)(((lane & 7) + ((lane & 16) >> 1)) * 144 + ((lane & 8) >> 3) * 16);
    const uint32_t bwa_off = 9216  + (uint32_t)(wx * 32 * 144) + bl;
    const uint32_t bwb_off = 27648 + (uint32_t)(wx * 32 * 144) + bl;

    float acc1[2][4][4], acc2[2][4][4];
#pragma unroll
    for (int mt = 0; mt < 2; mt++)
#pragma unroll
        for (int nt = 0; nt < 4; nt++)
#pragma unroll
            for (int r = 0; r < 4; r++) { acc1[mt][nt][r] = 0.f; acc2[mt][nt][r] = 0.f; }

#pragma unroll
    for (int p = 0; p < 4; p++) {
        const uint32_t sb = su + p * PG_STG;
#pragma unroll
        for (int k16 = 0; k16 < 4; k16++) {
            uint32_t af[2][4];
#pragma unroll
            for (int mt = 0; mt < 2; mt++)
                LDSM4(af[mt][0], af[mt][1], af[mt][2], af[mt][3],
                      sb + aw_off + mt * 16 * 144 + k16 * 32);
            uint32_t ba[2][4], bb[2][4];
#pragma unroll
            for (int q = 0; q < 2; q++) {
                LDSM4(ba[q][0], ba[q][1], ba[q][2], ba[q][3],
                      sb + bwa_off + q * 16 * 144 + k16 * 32);
                LDSM4(bb[q][0], bb[q][1], bb[q][2], bb[q][3],
                      sb + bwb_off + q * 16 * 144 + k16 * 32);
            }
#pragma unroll
            for (int mt = 0; mt < 2; mt++)
#pragma unroll
                for (int nt = 0; nt < 4; nt++) {
                    mma_f16(acc1[mt][nt], af[mt],
                            ba[nt >> 1][(nt & 1) * 2], ba[nt >> 1][(nt & 1) * 2 + 1]);
                    mma_f16(acc2[mt][nt], af[mt],
                            bb[nt >> 1][(nt & 1) * 2], bb[nt >> 1][(nt & 1) * 2 + 1]);
                }
        }
    }

    // write P1/P2 as half2
#pragma unroll
    for (int mt = 0; mt < 2; mt++)
#pragma unroll
        for (int nt = 0; nt < 4; nt++)
#pragma unroll
            for (int rr = 0; rr < 2; rr++) {
                int row = r0 + wy * 32 + mt * 16 + rr * 8 + gq;
                int col = c0 + wx * 32 + nt * 8 + gt * 2;
                __half2 v1 = __floats2half2_rn(acc1[mt][nt][rr * 2], acc1[mt][nt][rr * 2 + 1]);
                __half2 v2 = __floats2half2_rn(acc2[mt][nt][rr * 2], acc2[mt][nt][rr * 2 + 1]);
                *(__half2*)&g_P1h[(size_t)row * HA + col] = v1;
                *(__half2*)&g_P2h[(size_t)row * HA + col] = v2;
            }
}

// ---------------- kernel 3: Y1h = half(tanh.approx(base1 + P1h[i1] + P2h[i2])) ----------------
__global__ void k_y1() {
    int row = blockIdx.x;
    int b = row / KA;
    int id = g_idx[row];
    int i1 = id / N;
    int i2 = id - i1 * N;
    const __half2* p1 = (const __half2*)(g_P1h + (size_t)(b * N + i1) * HA);
    const __half2* p2 = (const __half2*)(g_P2h + (size_t)(b * N + i2) * HA);
    const float4* bs = (const float4*)(g_base1 + (size_t)b * HA);
    int t = threadIdx.x;                  // 256 threads x 4 cols
    float4 d = bs[t];
    float2 a0 = __half22float2(p1[2 * t]);
    float2 a1 = __half22float2(p1[2 * t + 1]);
    float2 c0 = __half22float2(p2[2 * t]);
    float2 c1 = __half22float2(p2[2 * t + 1]);
    __half2 h0 = __floats2half2_rn(tanh_fast(a0.x + c0.x + d.x), tanh_fast(a0.y + c0.y + d.y));
    __half2 h1 = __floats2half2_rn(tanh_fast(a1.x + c1.x + d.z), tanh_fast(a1.y + c1.y + d.w));
    __half2* y = (__half2*)(g_Y1h + (size_t)row * HA);
    y[2 * t]     = h0;
    y[2 * t + 1] = h1;
}

// ---------------- kernel 4: fp16 HMMA layer2 GEMM + fused layer3 ----------------
// CTA: 256 threads, 8 warps (2x4), tile 128x128, warp tile 64x32.
// K-slice 64 (4 x m16n8k16 per iter): NIT = 8 col-tiles x 16 slices = 128.
// 3 stages x 36864 B, wait(1). Two CTAs per SM. Row stride 144 B.
// Producer issue split: A-chunks after k16=0, B-chunks + commit after k16=1.
#define NSTG    3
#define STG_B   36864
#define OFFB_B  18432
#define NIT     128
#define L23_SMEM (NSTG * STG_B + 2048)    // 112640/CTA; x2 = 225280
extern __shared__ __align__(128) float smf[];

__global__ void __launch_bounds__(256, 2) k_l23(const float* __restrict__ ab2,
                                                const float* __restrict__ aW3) {
    const int tid = threadIdx.x;
    const int wid = tid >> 5;
    const int lane = tid & 31;
    const int wy = wid >> 2;     // 0..1 : 64-row band
    const int wx = wid & 3;      // 0..3 : 32-col band
    const size_t r0 = (size_t)blockIdx.x * 128;

    float* sred = smf + (NSTG * STG_B) / 4;        // [4][128]
    const uint32_t su = s2u(smf);

    const int gq = lane >> 2;
    const int gt = lane & 3;

    const uint32_t aw_off = (uint32_t)(wy * 64 * 144)
                          + (uint32_t)((lane & 15) * 144 + ((lane & 16) >> 4) * 16);
    const uint32_t bw_off = OFFB_B + (uint32_t)(wx * 32 * 144)
                          + (uint32_t)(((lane & 7) + ((lane & 16) >> 1)) * 144 + ((lane & 8) >> 3) * 16);

    const __half* Ybase = g_Y1h + r0 * HA;

    auto issue_A = [&](int p) {
        if (p < NIT) {
            const int k0 = (p & 15) * 64;
            const uint32_t sb = su + (uint32_t)(p % NSTG) * STG_B;
            const __half* Ab = Ybase + k0;
#pragma unroll
            for (int it = 0; it < 4; it++) {       // 128 rows x 8 chunks
                int idx = tid + it * 256;
                int row = idx >> 3, c = idx & 7;
                CPA16(sb + (uint32_t)(row * 144 + c * 16), Ab + (size_t)row * HA + c * 8);
            }
        }
    };
    auto issue_B = [&](int p) {
        if (p < NIT) {
            const int pct = p >> 4;                // col tile 0..7
            const int k0 = (p & 15) * 64;
            const uint32_t sb = su + (uint32_t)(p % NSTG) * STG_B;
            const __half* Bb = g_W2th + (size_t)(pct * 128) * HA + k0;
#pragma unroll
            for (int it = 0; it < 4; it++) {
                int idx = tid + it * 256;
                int row = idx >> 3, c = idx & 7;
                CPA16(sb + OFFB_B + (uint32_t)(row * 144 + c * 16), Bb + (size_t)row * HA + c * 8);
            }
        }
        CPA_COMMIT();
    };

    float lsum[8];
#pragma unroll
    for (int i = 0; i < 8; i++) lsum[i] = 0.f;

    float acc[4][4][4];
#pragma unroll
    for (int mt = 0; mt < 4; mt++)
#pragma unroll
        for (int nt = 0; nt < 4; nt++)
#pragma unroll
            for (int r = 0; r < 4; r++) acc[mt][nt][r] = 0.f;

    issue_A(0); issue_B(0);
    issue_A(1); issue_B(1);

    for (int it = 0; it < NIT; it++) {
        CPA_WAIT(1);
        __syncthreads();

        const uint32_t sb = su + (uint32_t)(it % NSTG) * STG_B;
        const uint32_t sA = sb + aw_off;
        const uint32_t sB = sb + bw_off;

#pragma unroll
        for (int k16 = 0; k16 < 4; k16++) {
            uint32_t af[4][4];
#pragma unroll
            for (int mt = 0; mt < 4; mt++)
                LDSM4(af[mt][0], af[mt][1], af[mt][2], af[mt][3],
                      sA + mt * 16 * 144 + k16 * 32);
            uint32_t bf[2][4];
#pragma unroll
            for (int p = 0; p < 2; p++)
                LDSM4(bf[p][0], bf[p][1], bf[p][2], bf[p][3],
                      sB + p * 16 * 144 + k16 * 32);
#pragma unroll
            for (int mt = 0; mt < 4; mt++)
#pragma unroll
                for (int nt = 0; nt < 4; nt++)
                    mma_f16(acc[mt][nt], af[mt],
                            bf[nt >> 1][(nt & 1) * 2], bf[nt >> 1][(nt & 1) * 2 + 1]);
            if (k16 == 0) issue_A(it + 2);
            if (k16 == 1) issue_B(it + 2);
        }

        if ((it & 15) == 15) {
            const int ct = it >> 4;
#pragma unroll
            for (int mt = 0; mt < 4; mt++)
#pragma unroll
                for (int rr = 0; rr < 2; rr++) {
                    float v = 0.f;
#pragma unroll
                    for (int nt = 0; nt < 4; nt++) {
                        int col = ct * 128 + wx * 32 + nt * 8 + gt * 2;
                        float b2a = __ldg(ab2 + col);
                        float b2b = __ldg(ab2 + col + 1);
                        float w3a = __ldg(aW3 + col);
                        float w3b = __ldg(aW3 + col + 1);
                        float x0 = acc[mt][nt][rr * 2 + 0] + b2a;
                        float x1 = acc[mt][nt][rr * 2 + 1] + b2b;
                        v += tanh_fast(x0) * w3a + tanh_fast(x1) * w3b;
                    }
                    lsum[mt * 2 + rr] += v;
                }
#pragma unroll
            for (int mt = 0; mt < 4; mt++)
#pragma unroll
                for (int nt = 0; nt < 4; nt++)
#pragma unroll
                    for (int r = 0; r < 4; r++) acc[mt][nt][r] = 0.f;
        }
    }

#pragma unroll
    for (int i = 0; i < 8; i++) {
        float v = lsum[i];
        v += __shfl_xor_sync(0xffffffffu, v, 1);
        v += __shfl_xor_sync(0xffffffffu, v, 2);
        if (gt == 0) {
            int lr = wy * 64 + (i >> 1) * 16 + (i & 1) * 8 + gq;
            sred[wx * 128 + lr] = v;
        }
    }
    __syncthreads();
    if (tid < 128) {
        float v = (sred[tid] + sred[128 + tid]) + (sred[256 + tid] + sred[384 + tid]);
        g_logits[r0 + tid] = v;
    }
}

// ---------------- kernel 5: value head ----------------
__global__ void k_value(const float* __restrict__ ef,
                        const float* __restrict__ cW1, const float* __restrict__ cb1,
                        const float* __restrict__ cW2, const float* __restrict__ cb2,
                        const float* __restrict__ cW3, const float* __restrict__ cb3,
                        float* __restrict__ out) {
    __shared__ float sg[H];
    __shared__ float h1[HC];
    __shared__ float h2[HC];
    __shared__ float sr[16];
    int b = blockIdx.x;
    int tid = threadIdx.x;  // 512
    if (tid < H) sg[tid] = ef[(size_t)b * EF_BSTRIDE + tid];
    __syncthreads();
    float acc = cb1[tid];
#pragma unroll 8
    for (int h = 0; h < H; h++) acc += sg[h] * cW1[h * HC + tid];
    h1[tid] = tanhf(acc);
    __syncthreads();
    float acc2 = cb2[tid];
#pragma unroll 8
    for (int h = 0; h < HC; h++) acc2 += h1[h] * cW2[h * HC + tid];
    h2[tid] = tanhf(acc2);
    __syncthreads();
    float p = h2[tid] * cW3[tid];
#pragma unroll
    for (int o = 16; o; o >>= 1) p += __shfl_xor_sync(0xffffffffu, p, o);
    if ((tid & 31) == 0) sr[tid >> 5] = p;
    __syncthreads();
    if (tid < 16) {
        float v = sr[tid];
#pragma unroll
        for (int o = 8; o; o >>= 1) v += __shfl_xor_sync(0x0000ffffu, v, o);
        if (tid == 0) out[OUT_FILLED + b] = v + cb3[0];
    }
}

// ---------------- kernel 6: softmax + zero + scatter (fused) ----------------
__global__ void k_softmax(float* __restrict__ out, const float* __restrict__ ab3) {
    __shared__ float slog[KA];
    __shared__ float sred2[32];
    __shared__ float sbcast;
    int b = blockIdx.x;
    int tid = threadIdx.x;  // 1024
    float b3 = ab3[0];

    for (int k = tid; k < NN; k += 1024)
        out[(size_t)b * NN + k] = 0.f;

    for (int k = tid; k < KA; k += 1024)
        slog[k] = g_logits[b * KA + k] + b3;
    __syncthreads();

    float m = -3.4e38f;
    for (int k = tid; k < KA; k += 1024) m = fmaxf(m, slog[k]);
#pragma unroll
    for (int o = 16; o; o >>= 1) m = fmaxf(m, __shfl_xor_sync(0xffffffffu, m, o));
    if ((tid & 31) == 0) sred2[tid >> 5] = m;
    __syncthreads();
    if (tid < 32) {
        float v = sred2[tid];
#pragma unroll
        for (int o = 16; o; o >>= 1) v = fmaxf(v, __shfl_xor_sync(0xffffffffu, v, o));
        if (tid == 0) sbcast = v;
    }
    __syncthreads();
    float gmax = sbcast;

    float s = 0.f;
    for (int k = tid; k < KA; k += 1024) s += expf(slog[k] - gmax);
#pragma unroll
    for (int o = 16; o; o >>= 1) s += __shfl_xor_sync(0xffffffffu, s, o);
    if ((tid & 31) == 0) sred2[tid >> 5] = s;
    __syncthreads();
    if (tid < 32) {
        float v = sred2[tid];
#pragma unroll
        for (int o = 16; o; o >>= 1) v += __shfl_xor_sync(0xffffffffu, v, o);
        if (tid == 0) sbcast = v;
    }
    __syncthreads();
    float inv = 1.0f / sbcast;

    for (int k = tid; k < KA; k += 1024) {
        int j = g_idx[b * KA + k];
        out[(size_t)b * NN + j] = expf(slog[k] - gmax) * inv;
    }
}

// ---------------- launch ----------------
extern "C" void kernel_launch(void* const* d_in, const int* in_sizes, int n_in,
                              void* d_out, int out_size) {
    const float* ef  = (const float*)d_in[0];
    const float* aW1 = (const float*)d_in[1];
    const float* ab1 = (const float*)d_in[2];
    const float* aW2 = (const float*)d_in[3];
    const float* ab2 = (const float*)d_in[4];
    const float* aW3 = (const float*)d_in[5];
    const float* ab3 = (const float*)d_in[6];
    const float* cW1 = (const float*)d_in[7];
    const float* cb1 = (const float*)d_in[8];
    const float* cW2 = (const float*)d_in[9];
    const float* cb2 = (const float*)d_in[10];
    const float* cW3 = (const float*)d_in[11];
    const float* cb3 = (const float*)d_in[12];
    float* out = (float*)d_out;

    cudaFuncSetAttribute(k_l23, cudaFuncAttributeMaxDynamicSharedMemorySize, L23_SMEM);
    cudaFuncSetAttribute(k_pgemm_h, cudaFuncAttributeMaxDynamicSharedMemorySize, PG_SMEM);

    k_prep<<<1896, 256>>>(ef, aW1, ab1, aW2);           // launch 1
    k_pgemm_h<<<dim3(50, 8), 256, PG_SMEM>>>();         // launch 2
    k_y1<<<B * KA, 256>>>();                            // launch 3
    k_l23<<<1250, 256, L23_SMEM>>>(ab2, aW3);           // launch 4 (ncu capture)
    k_value<<<B, 512>>>(ef, cW1, cb1, cW2, cb2, cW3, cb3, out);
    k_softmax<<<B, 1024>>>(out, ab3);
}